// round 1
// baseline (speedup 1.0000x reference)
#include <cuda_runtime.h>
#include <math.h>

#define LQ     9216              // 96*96
#define NBATCH 2
#define M_TOT  (NBATCH * LQ)     // 18432
#define CH     256
#define HEADS  8
#define NP     25
#define DH     32
#define HID    1024

// ---------------- scratch (static device globals; no allocation) ----------------
__device__ float g_q    [M_TOT * CH];
__device__ float g_val  [M_TOT * CH];
__device__ float g_off  [M_TOT * HEADS * NP * 2];
__device__ float g_logit[M_TOT * HEADS * NP];
__device__ float g_attn [M_TOT * CH];
__device__ float g_x1   [M_TOT * CH];
__device__ float g_y    [M_TOT * CH];
__device__ float g_h1   [M_TOT * HID];

// ---------------- LayerNorm: one warp per row of 256 channels ----------------
__global__ void ln_kernel(const float* __restrict__ x,
                          const float* __restrict__ g,
                          const float* __restrict__ b,
                          float* __restrict__ out) {
    int row  = blockIdx.x * blockDim.y + threadIdx.y;
    int lane = threadIdx.x;
    const float* xr = x + (size_t)row * CH;
    float v[8];
    float s = 0.f, sq = 0.f;
#pragma unroll
    for (int i = 0; i < 8; i++) {
        v[i] = xr[lane + 32 * i];
        s  += v[i];
        sq += v[i] * v[i];
    }
#pragma unroll
    for (int o = 16; o > 0; o >>= 1) {
        s  += __shfl_xor_sync(0xffffffffu, s,  o);
        sq += __shfl_xor_sync(0xffffffffu, sq, o);
    }
    float mean = s * (1.f / 256.f);
    float var  = sq * (1.f / 256.f) - mean * mean;
    float rstd = rsqrtf(var + 1e-5f);
    float* outr = out + (size_t)row * CH;
#pragma unroll
    for (int i = 0; i < 8; i++) {
        int c = lane + 32 * i;
        outr[c] = (v[i] - mean) * rstd * g[c] + b[c];
    }
}

// ---------------- generic tiled fp32 GEMM  C = A[M,K] @ B[K,N] + bias ----------------
// epi: 0 = bias only, 1 = bias + exact GELU, 2 = bias + residual R[M,N]
#define BM 64
#define BN 64
#define BK 16
__global__ void __launch_bounds__(256)
gemm_kernel(const float* __restrict__ A, const float* __restrict__ B,
            const float* __restrict__ bias, const float* __restrict__ R,
            float* __restrict__ Cout, int M, int N, int K, int epi) {
    __shared__ float As[BM][BK + 1];
    __shared__ float Bs[BK][BN];
    int tid = threadIdx.x;
    int tx = tid & 15, ty = tid >> 4;
    int row0 = blockIdx.y * BM;
    int col0 = blockIdx.x * BN;
    float acc[4][4] = {};

    for (int k0 = 0; k0 < K; k0 += BK) {
        // load A tile (M is always a multiple of 64)
#pragma unroll
        for (int i = 0; i < 4; i++) {
            int idx = tid + i * 256;
            int r = idx >> 4, c = idx & 15;
            As[r][c] = A[(size_t)(row0 + r) * K + k0 + c];
        }
        // load B tile (guard N: 400/200 tails)
#pragma unroll
        for (int i = 0; i < 4; i++) {
            int idx = tid + i * 256;
            int r = idx >> 6, c = idx & 63;
            int col = col0 + c;
            Bs[r][c] = (col < N) ? B[(size_t)(k0 + r) * N + col] : 0.f;
        }
        __syncthreads();
#pragma unroll
        for (int k = 0; k < BK; k++) {
            float a[4], bb[4];
#pragma unroll
            for (int i = 0; i < 4; i++) a[i]  = As[ty * 4 + i][k];
#pragma unroll
            for (int j = 0; j < 4; j++) bb[j] = Bs[k][tx * 4 + j];
#pragma unroll
            for (int i = 0; i < 4; i++)
#pragma unroll
                for (int j = 0; j < 4; j++)
                    acc[i][j] = fmaf(a[i], bb[j], acc[i][j]);
        }
        __syncthreads();
    }

#pragma unroll
    for (int i = 0; i < 4; i++) {
        int row = row0 + ty * 4 + i;
#pragma unroll
        for (int j = 0; j < 4; j++) {
            int col = col0 + tx * 4 + j;
            if (col < N) {
                float v = acc[i][j] + bias[col];
                if (epi == 1) {
                    v = 0.5f * v * (1.f + erff(v * 0.70710678118654752440f));
                } else if (epi == 2) {
                    v += R[(size_t)row * N + col];
                }
                Cout[(size_t)row * N + col] = v;
            }
        }
    }
}

// ---------------- fused softmax + deformable bilinear attention ----------------
// block = (32, 8): warp per head, lane per channel-within-head.
// out[n,q, h*32+lane] = sum_p softmax(logits)[p] * bilinear(value, loc_p)[lane]
__global__ void deform_kernel(const float* __restrict__ value,
                              const float* __restrict__ off,
                              const float* __restrict__ logits,
                              const float* __restrict__ refp,
                              float* __restrict__ out) {
    int bq   = blockIdx.x;        // n*LQ + q
    int n    = bq / LQ;
    int h    = threadIdx.y;
    int lane = threadIdx.x;

    const float* offr = off    + (size_t)bq * (HEADS * NP * 2) + h * (NP * 2);
    const float* logr = logits + (size_t)bq * (HEADS * NP)     + h * NP;
    float rx = refp[(size_t)bq * 2 + 0];
    float ry = refp[(size_t)bq * 2 + 1];

    // in-warp softmax over 25 points (lanes 0..24 hold logits)
    float lg = (lane < NP) ? logr[lane] : -1e30f;
    float mx = lg;
#pragma unroll
    for (int o = 16; o > 0; o >>= 1) mx = fmaxf(mx, __shfl_xor_sync(0xffffffffu, mx, o));
    float e = (lane < NP) ? expf(lg - mx) : 0.f;
    float sum = e;
#pragma unroll
    for (int o = 16; o > 0; o >>= 1) sum += __shfl_xor_sync(0xffffffffu, sum, o);
    float awn = e / sum;

    const float* vb = value + (size_t)n * LQ * CH + h * DH + lane;

    float acc = 0.f;
    for (int p = 0; p < NP; p++) {
        float ap = __shfl_sync(0xffffffffu, awn, p);
        // gx = (rx + ox/96)*96 - 0.5 = rx*96 + ox - 0.5
        float gx = fmaf(rx, 96.f, offr[2 * p]     - 0.5f);
        float gy = fmaf(ry, 96.f, offr[2 * p + 1] - 0.5f);
        float x0f = floorf(gx), y0f = floorf(gy);
        float fx = gx - x0f, fy = gy - y0f;
        int x0 = (int)x0f, y0 = (int)y0f;
        int x1 = x0 + 1,   y1 = y0 + 1;
        bool vx0 = (x0 >= 0) && (x0 <= 95);
        bool vx1 = (x1 >= 0) && (x1 <= 95);
        bool vy0 = (y0 >= 0) && (y0 <= 95);
        bool vy1 = (y1 >= 0) && (y1 <= 95);
        float w00 = (1.f - fx) * (1.f - fy) * ap;
        float w10 = fx * (1.f - fy) * ap;
        float w01 = (1.f - fx) * fy * ap;
        float w11 = fx * fy * ap;
        if (vx0 && vy0) acc = fmaf(w00, vb[(size_t)(y0 * 96 + x0) * CH], acc);
        if (vx1 && vy0) acc = fmaf(w10, vb[(size_t)(y0 * 96 + x1) * CH], acc);
        if (vx0 && vy1) acc = fmaf(w01, vb[(size_t)(y1 * 96 + x0) * CH], acc);
        if (vx1 && vy1) acc = fmaf(w11, vb[(size_t)(y1 * 96 + x1) * CH], acc);
    }
    out[(size_t)bq * CH + h * DH + lane] = acc;
}

// ---------------- launch ----------------
extern "C" void kernel_launch(void* const* d_in, const int* in_sizes, int n_in,
                              void* d_out, int out_size) {
    const float* x      = (const float*)d_in[0];
    const float* refp   = (const float*)d_in[1];
    // d_in[2] spatial_shapes, d_in[3] level_start_index: constants, unused
    const float* ln1_g  = (const float*)d_in[4];
    const float* ln1_b  = (const float*)d_in[5];
    const float* w_off  = (const float*)d_in[6];
    const float* b_off  = (const float*)d_in[7];
    const float* w_attn = (const float*)d_in[8];
    const float* b_attn = (const float*)d_in[9];
    const float* w_val  = (const float*)d_in[10];
    const float* b_val  = (const float*)d_in[11];
    const float* w_out  = (const float*)d_in[12];
    const float* b_out  = (const float*)d_in[13];
    const float* ln2_g  = (const float*)d_in[14];
    const float* ln2_b  = (const float*)d_in[15];
    const float* w_fc1  = (const float*)d_in[16];
    const float* b_fc1  = (const float*)d_in[17];
    const float* w_fc2  = (const float*)d_in[18];
    const float* b_fc2  = (const float*)d_in[19];
    float* out = (float*)d_out;

    float *p_q, *p_val, *p_off, *p_logit, *p_attn, *p_x1, *p_y, *p_h1;
    cudaGetSymbolAddress((void**)&p_q,     g_q);
    cudaGetSymbolAddress((void**)&p_val,   g_val);
    cudaGetSymbolAddress((void**)&p_off,   g_off);
    cudaGetSymbolAddress((void**)&p_logit, g_logit);
    cudaGetSymbolAddress((void**)&p_attn,  g_attn);
    cudaGetSymbolAddress((void**)&p_x1,    g_x1);
    cudaGetSymbolAddress((void**)&p_y,     g_y);
    cudaGetSymbolAddress((void**)&p_h1,    g_h1);

    dim3 lnBlock(32, 8);
    int  lnGrid = M_TOT / 8;

    // 1) LN1: x -> q
    ln_kernel<<<lnGrid, lnBlock>>>(x, ln1_g, ln1_b, p_q);

    // 2) value = q @ w_val + b_val
    gemm_kernel<<<dim3((CH + BN - 1) / BN, M_TOT / BM), 256>>>(
        p_q, w_val, b_val, nullptr, p_val, M_TOT, CH, CH, 0);
    // 3) off = q @ w_off + b_off   (N = 400)
    gemm_kernel<<<dim3((HEADS * NP * 2 + BN - 1) / BN, M_TOT / BM), 256>>>(
        p_q, w_off, b_off, nullptr, p_off, M_TOT, HEADS * NP * 2, CH, 0);
    // 4) logits = q @ w_attn + b_attn   (N = 200)
    gemm_kernel<<<dim3((HEADS * NP + BN - 1) / BN, M_TOT / BM), 256>>>(
        p_q, w_attn, b_attn, nullptr, p_logit, M_TOT, HEADS * NP, CH, 0);

    // 5) fused softmax + deformable sampling + attention-weighted sum
    deform_kernel<<<M_TOT, dim3(32, 8)>>>(p_val, p_off, p_logit, refp, p_attn);

    // 6) x1 = shortcut + attn @ w_out + b_out
    gemm_kernel<<<dim3((CH + BN - 1) / BN, M_TOT / BM), 256>>>(
        p_attn, w_out, b_out, x, p_x1, M_TOT, CH, CH, 2);

    // 7) LN2: x1 -> y
    ln_kernel<<<lnGrid, lnBlock>>>(p_x1, ln2_g, ln2_b, p_y);

    // 8) h1 = gelu(y @ w_fc1 + b_fc1)
    gemm_kernel<<<dim3(HID / BN, M_TOT / BM), 256>>>(
        p_y, w_fc1, b_fc1, nullptr, p_h1, M_TOT, HID, CH, 1);

    // 9) out = x1 + h1 @ w_fc2 + b_fc2
    gemm_kernel<<<dim3(CH / BN, M_TOT / BM), 256>>>(
        p_h1, w_fc2, b_fc2, p_x1, out, M_TOT, CH, HID, 2);
}

// round 2
// speedup vs baseline: 2.1782x; 2.1782x over previous
#include <cuda_runtime.h>
#include <math.h>

#define LQ     9216
#define NBATCH 2
#define M_TOT  (NBATCH * LQ)     // 18432
#define CH     256
#define HEADS  8
#define NP     25
#define DH     32
#define HID    1024
#define NQP    1024              // padded fused q-projection width: [val 256 | off 400 | logit 200 | pad 168]
#define OFF_COL  256
#define LOG_COL  656

// ---------------- scratch ----------------
__device__ float g_q   [M_TOT * CH];     // tf32-rounded LN1 out
__device__ float g_proj[M_TOT * NQP];    // fused val/off/logit
__device__ float g_attn[M_TOT * CH];     // tf32-rounded deform out
__device__ float g_x1  [M_TOT * CH];
__device__ float g_y   [M_TOT * CH];     // tf32-rounded LN2 out
__device__ float g_h1  [M_TOT * HID];    // tf32-rounded gelu out
__device__ float g_wq  [CH * NQP];       // fused+rounded weights
__device__ float g_bq  [NQP];
__device__ float g_wout[CH * CH];
__device__ float g_wfc1[CH * HID];
__device__ float g_wfc2[HID * CH];

__device__ __forceinline__ float tf32r(float x) {
    unsigned u;
    asm("cvt.rna.tf32.f32 %0, %1;" : "=r"(u) : "f"(x));
    return __uint_as_float(u);
}

__device__ __forceinline__ void cp16(void* s, const void* g) {
    unsigned sa = (unsigned)__cvta_generic_to_shared(s);
    asm volatile("cp.async.cg.shared.global [%0], [%1], 16;\n" :: "r"(sa), "l"(g));
}

__device__ __forceinline__ void mma_tf32(float c[4], unsigned a0, unsigned a1,
                                         unsigned a2, unsigned a3,
                                         unsigned b0, unsigned b1) {
    asm volatile(
        "mma.sync.aligned.m16n8k8.row.col.f32.tf32.tf32.f32 "
        "{%0,%1,%2,%3},{%4,%5,%6,%7},{%8,%9},{%0,%1,%2,%3};\n"
        : "+f"(c[0]), "+f"(c[1]), "+f"(c[2]), "+f"(c[3])
        : "r"(a0), "r"(a1), "r"(a2), "r"(a3), "r"(b0), "r"(b1));
}

// ---------------- prep: fuse + tf32-round weights ----------------
__global__ void prep_wq(const float* __restrict__ w_val, const float* __restrict__ w_off,
                        const float* __restrict__ w_attn, const float* __restrict__ b_val,
                        const float* __restrict__ b_off, const float* __restrict__ b_attn,
                        float* __restrict__ wq, float* __restrict__ bq) {
    int idx = blockIdx.x * blockDim.x + threadIdx.x;   // over 256*1024
    int row = idx >> 10, col = idx & 1023;
    float v;
    if      (col < 256) v = w_val [row * 256 + col];
    else if (col < 656) v = w_off [row * 400 + (col - 256)];
    else if (col < 856) v = w_attn[row * 200 + (col - 656)];
    else                v = 0.f;
    wq[idx] = tf32r(v);
    if (row == 0) {
        float b;
        if      (col < 256) b = b_val [col];
        else if (col < 656) b = b_off [col - 256];
        else if (col < 856) b = b_attn[col - 656];
        else                b = 0.f;
        bq[col] = b;
    }
}

__global__ void round_w(const float* __restrict__ src, float* __restrict__ dst, int n) {
    int i = blockIdx.x * blockDim.x + threadIdx.x;
    if (i < n) dst[i] = tf32r(src[i]);
}

// ---------------- LayerNorm (warp/row), tf32-rounded output ----------------
__global__ void ln_kernel(const float* __restrict__ x, const float* __restrict__ g,
                          const float* __restrict__ b, float* __restrict__ out) {
    int row  = blockIdx.x * blockDim.y + threadIdx.y;
    int lane = threadIdx.x;
    const float* xr = x + (size_t)row * CH;
    float v[8], s = 0.f, sq = 0.f;
#pragma unroll
    for (int i = 0; i < 8; i++) {
        v[i] = xr[lane + 32 * i];
        s += v[i]; sq += v[i] * v[i];
    }
#pragma unroll
    for (int o = 16; o > 0; o >>= 1) {
        s  += __shfl_xor_sync(0xffffffffu, s,  o);
        sq += __shfl_xor_sync(0xffffffffu, sq, o);
    }
    float mean = s * (1.f / 256.f);
    float var  = sq * (1.f / 256.f) - mean * mean;
    float rstd = rsqrtf(var + 1e-5f);
    float* outr = out + (size_t)row * CH;
#pragma unroll
    for (int i = 0; i < 8; i++) {
        int c = lane + 32 * i;
        outr[c] = tf32r((v[i] - mean) * rstd * g[c] + b[c]);
    }
}

// ---------------- TF32 tensor-core GEMM: C = A[M,K]@B[K,N] + bias ----------------
// epi: 0=bias, 1=bias+gelu+tf32round, 2=bias+residual
#define GBM 128
#define GBN 128
#define GBK 16
#define A_LD 20
#define B_LD 132

__global__ void __launch_bounds__(256, 2)
gemm_tf32(const float* __restrict__ A, const float* __restrict__ B,
          const float* __restrict__ bias, const float* __restrict__ R,
          float* __restrict__ C, int M, int N, int K, int epi) {
    __shared__ float As[2][GBM * A_LD];
    __shared__ float Bs[2][GBK * B_LD];
    int tid = threadIdx.x, lane = tid & 31, warp = tid >> 5;
    int wr = warp >> 1, wc = warp & 1;
    int row0 = blockIdx.y * GBM, col0 = blockIdx.x * GBN;
    int gID = lane >> 2, tig = lane & 3;

    int ar = tid >> 2, ac = (tid & 3) * 4;
    int bk = tid >> 5, bn = (tid & 31) * 4;
    const float* Ag = A + (size_t)(row0 + ar) * K + ac;
    const float* Bg = B + (size_t)bk * N + col0 + bn;

    float acc[2][8][4] = {};
    int ntile = K / GBK;

    cp16(&As[0][ar * A_LD + ac], Ag);
    cp16(&As[0][(ar + 64) * A_LD + ac], Ag + (size_t)64 * K);
    cp16(&Bs[0][bk * B_LD + bn], Bg);
    cp16(&Bs[0][(bk + 8) * B_LD + bn], Bg + (size_t)8 * N);
    asm volatile("cp.async.commit_group;\n");

    for (int t = 0; t < ntile; t++) {
        if (t + 1 < ntile) {
            const float* Ag2 = Ag + (t + 1) * GBK;
            const float* Bg2 = Bg + (size_t)(t + 1) * GBK * N;
            int s = (t + 1) & 1;
            cp16(&As[s][ar * A_LD + ac], Ag2);
            cp16(&As[s][(ar + 64) * A_LD + ac], Ag2 + (size_t)64 * K);
            cp16(&Bs[s][bk * B_LD + bn], Bg2);
            cp16(&Bs[s][(bk + 8) * B_LD + bn], Bg2 + (size_t)8 * N);
            asm volatile("cp.async.commit_group;\n");
            asm volatile("cp.async.wait_group 1;\n");
        } else {
            asm volatile("cp.async.wait_group 0;\n");
        }
        __syncthreads();
        const float* as = As[t & 1];
        const float* bs = Bs[t & 1];
#pragma unroll
        for (int ks = 0; ks < 2; ks++) {
            int k8 = ks * 8;
            unsigned af[2][4];
#pragma unroll
            for (int mt = 0; mt < 2; mt++) {
                int mrow = wr * 32 + mt * 16 + gID;
                af[mt][0] = __float_as_uint(as[mrow * A_LD + k8 + tig]);
                af[mt][1] = __float_as_uint(as[(mrow + 8) * A_LD + k8 + tig]);
                af[mt][2] = __float_as_uint(as[mrow * A_LD + k8 + tig + 4]);
                af[mt][3] = __float_as_uint(as[(mrow + 8) * A_LD + k8 + tig + 4]);
            }
#pragma unroll
            for (int nt = 0; nt < 8; nt++) {
                int ncol = wc * 64 + nt * 8 + gID;
                unsigned b0 = __float_as_uint(bs[(k8 + tig) * B_LD + ncol]);
                unsigned b1 = __float_as_uint(bs[(k8 + tig + 4) * B_LD + ncol]);
                mma_tf32(acc[0][nt], af[0][0], af[0][1], af[0][2], af[0][3], b0, b1);
                mma_tf32(acc[1][nt], af[1][0], af[1][1], af[1][2], af[1][3], b0, b1);
            }
        }
        __syncthreads();
    }

#pragma unroll
    for (int mt = 0; mt < 2; mt++) {
#pragma unroll
        for (int nt = 0; nt < 8; nt++) {
            int row = row0 + wr * 32 + mt * 16 + gID;
            int col = col0 + wc * 64 + nt * 8 + tig * 2;
            float b0 = bias[col], b1 = bias[col + 1];
            float v0 = acc[mt][nt][0] + b0;
            float v1 = acc[mt][nt][1] + b1;
            float v2 = acc[mt][nt][2] + b0;
            float v3 = acc[mt][nt][3] + b1;
            if (epi == 1) {
                v0 = tf32r(0.5f * v0 * (1.f + erff(v0 * 0.70710678118654752440f)));
                v1 = tf32r(0.5f * v1 * (1.f + erff(v1 * 0.70710678118654752440f)));
                v2 = tf32r(0.5f * v2 * (1.f + erff(v2 * 0.70710678118654752440f)));
                v3 = tf32r(0.5f * v3 * (1.f + erff(v3 * 0.70710678118654752440f)));
            } else if (epi == 2) {
                const float* r0 = R + (size_t)row * N + col;
                const float* r1 = R + (size_t)(row + 8) * N + col;
                v0 += r0[0]; v1 += r0[1]; v2 += r1[0]; v3 += r1[1];
            }
            float* d0 = C + (size_t)row * N + col;
            float* d1 = C + (size_t)(row + 8) * N + col;
            d0[0] = v0; d0[1] = v1; d1[0] = v2; d1[1] = v3;
        }
    }
}

// ---------------- fused softmax + deformable bilinear attention ----------------
__global__ void deform_kernel(const float* __restrict__ proj,
                              const float* __restrict__ refp,
                              float* __restrict__ out) {
    int bq   = blockIdx.x;
    int n    = bq / LQ;
    int h    = threadIdx.y;
    int lane = threadIdx.x;

    const float* offr = proj + (size_t)bq * NQP + OFF_COL + h * (NP * 2);
    const float* logr = proj + (size_t)bq * NQP + LOG_COL + h * NP;
    float rx = refp[(size_t)bq * 2 + 0];
    float ry = refp[(size_t)bq * 2 + 1];

    float lg = (lane < NP) ? logr[lane] : -1e30f;
    float mx = lg;
#pragma unroll
    for (int o = 16; o > 0; o >>= 1) mx = fmaxf(mx, __shfl_xor_sync(0xffffffffu, mx, o));
    float e = (lane < NP) ? expf(lg - mx) : 0.f;
    float sum = e;
#pragma unroll
    for (int o = 16; o > 0; o >>= 1) sum += __shfl_xor_sync(0xffffffffu, sum, o);
    float awn = e / sum;

    const float* vb = proj + (size_t)n * LQ * NQP + h * DH + lane;

    float acc = 0.f;
    for (int p = 0; p < NP; p++) {
        float ap = __shfl_sync(0xffffffffu, awn, p);
        float gx = fmaf(rx, 96.f, offr[2 * p]     - 0.5f);
        float gy = fmaf(ry, 96.f, offr[2 * p + 1] - 0.5f);
        float x0f = floorf(gx), y0f = floorf(gy);
        float fx = gx - x0f, fy = gy - y0f;
        int x0 = (int)x0f, y0 = (int)y0f;
        int x1 = x0 + 1,   y1 = y0 + 1;
        bool vx0 = (x0 >= 0) && (x0 <= 95);
        bool vx1 = (x1 >= 0) && (x1 <= 95);
        bool vy0 = (y0 >= 0) && (y0 <= 95);
        bool vy1 = (y1 >= 0) && (y1 <= 95);
        float w00 = (1.f - fx) * (1.f - fy) * ap;
        float w10 = fx * (1.f - fy) * ap;
        float w01 = (1.f - fx) * fy * ap;
        float w11 = fx * fy * ap;
        if (vx0 && vy0) acc = fmaf(w00, vb[(size_t)(y0 * 96 + x0) * NQP], acc);
        if (vx1 && vy0) acc = fmaf(w10, vb[(size_t)(y0 * 96 + x1) * NQP], acc);
        if (vx0 && vy1) acc = fmaf(w01, vb[(size_t)(y1 * 96 + x0) * NQP], acc);
        if (vx1 && vy1) acc = fmaf(w11, vb[(size_t)(y1 * 96 + x1) * NQP], acc);
    }
    out[(size_t)bq * CH + h * DH + lane] = tf32r(acc);
}

// ---------------- launch ----------------
extern "C" void kernel_launch(void* const* d_in, const int* in_sizes, int n_in,
                              void* d_out, int out_size) {
    const float* x      = (const float*)d_in[0];
    const float* refp   = (const float*)d_in[1];
    const float* ln1_g  = (const float*)d_in[4];
    const float* ln1_b  = (const float*)d_in[5];
    const float* w_off  = (const float*)d_in[6];
    const float* b_off  = (const float*)d_in[7];
    const float* w_attn = (const float*)d_in[8];
    const float* b_attn = (const float*)d_in[9];
    const float* w_val  = (const float*)d_in[10];
    const float* b_val  = (const float*)d_in[11];
    const float* w_out  = (const float*)d_in[12];
    const float* b_out  = (const float*)d_in[13];
    const float* ln2_g  = (const float*)d_in[14];
    const float* ln2_b  = (const float*)d_in[15];
    const float* w_fc1  = (const float*)d_in[16];
    const float* b_fc1  = (const float*)d_in[17];
    const float* w_fc2  = (const float*)d_in[18];
    const float* b_fc2  = (const float*)d_in[19];
    float* out = (float*)d_out;

    float *p_q, *p_proj, *p_attn, *p_x1, *p_y, *p_h1;
    float *p_wq, *p_bq, *p_wout, *p_wfc1, *p_wfc2;
    cudaGetSymbolAddress((void**)&p_q,    g_q);
    cudaGetSymbolAddress((void**)&p_proj, g_proj);
    cudaGetSymbolAddress((void**)&p_attn, g_attn);
    cudaGetSymbolAddress((void**)&p_x1,   g_x1);
    cudaGetSymbolAddress((void**)&p_y,    g_y);
    cudaGetSymbolAddress((void**)&p_h1,   g_h1);
    cudaGetSymbolAddress((void**)&p_wq,   g_wq);
    cudaGetSymbolAddress((void**)&p_bq,   g_bq);
    cudaGetSymbolAddress((void**)&p_wout, g_wout);
    cudaGetSymbolAddress((void**)&p_wfc1, g_wfc1);
    cudaGetSymbolAddress((void**)&p_wfc2, g_wfc2);

    // weight prep (tf32 rounding + fusion)
    prep_wq<<<CH * NQP / 256, 256>>>(w_val, w_off, w_attn, b_val, b_off, b_attn, p_wq, p_bq);
    round_w<<<CH * CH   / 256, 256>>>(w_out,  p_wout, CH * CH);
    round_w<<<CH * HID  / 256, 256>>>(w_fc1,  p_wfc1, CH * HID);
    round_w<<<HID * CH  / 256, 256>>>(w_fc2,  p_wfc2, HID * CH);

    dim3 lnBlock(32, 8);
    int  lnGrid = M_TOT / 8;

    // 1) LN1
    ln_kernel<<<lnGrid, lnBlock>>>(x, ln1_g, ln1_b, p_q);
    // 2) fused q-projection: [val | off | logits]
    gemm_tf32<<<dim3(NQP / GBN, M_TOT / GBM), 256>>>(
        p_q, p_wq, p_bq, nullptr, p_proj, M_TOT, NQP, CH, 0);
    // 3) deform attention
    deform_kernel<<<M_TOT, dim3(32, 8)>>>(p_proj, refp, p_attn);
    // 4) x1 = x + attn @ w_out + b_out
    gemm_tf32<<<dim3(CH / GBN, M_TOT / GBM), 256>>>(
        p_attn, p_wout, b_out, x, p_x1, M_TOT, CH, CH, 2);
    // 5) LN2
    ln_kernel<<<lnGrid, lnBlock>>>(p_x1, ln2_g, ln2_b, p_y);
    // 6) h1 = gelu(y @ w_fc1 + b_fc1)
    gemm_tf32<<<dim3(HID / GBN, M_TOT / GBM), 256>>>(
        p_y, p_wfc1, b_fc1, nullptr, p_h1, M_TOT, HID, CH, 1);
    // 7) out = x1 + h1 @ w_fc2 + b_fc2
    gemm_tf32<<<dim3(CH / GBN, M_TOT / GBM), 256>>>(
        p_h1, p_wfc2, b_fc2, p_x1, out, M_TOT, CH, HID, 2);
}

// round 3
// speedup vs baseline: 2.3283x; 1.0689x over previous
#include <cuda_runtime.h>
#include <cuda_bf16.h>
#include <math.h>

#define LQ     9216
#define NBATCH 2
#define M_TOT  (NBATCH * LQ)     // 18432
#define CH     256
#define HEADS  8
#define NP     25
#define DH     32
#define HID    1024
#define NQP    1024              // [val 256 | off 400 | logit 200 | pad 168]
#define OFF_COL  256
#define LOG_COL  656

// ---------------- scratch ----------------
__device__ float          g_q   [M_TOT * CH];
__device__ float          g_proj[M_TOT * NQP];
__device__ __nv_bfloat16  g_valh[M_TOT * CH];
__device__ float          g_attn[M_TOT * CH];
__device__ float          g_x1  [M_TOT * CH];
__device__ float          g_y   [M_TOT * CH];
__device__ float          g_h1  [M_TOT * HID];
__device__ float          g_wq  [CH * NQP];
__device__ float          g_bq  [NQP];

__device__ __forceinline__ float tf32r(float x) {
    unsigned u;
    asm("cvt.rna.tf32.f32 %0, %1;" : "=r"(u) : "f"(x));
    return __uint_as_float(u);
}

__device__ __forceinline__ void cp16(void* s, const void* g) {
    unsigned sa = (unsigned)__cvta_generic_to_shared(s);
    asm volatile("cp.async.cg.shared.global [%0], [%1], 16;\n" :: "r"(sa), "l"(g));
}

__device__ __forceinline__ void mma_tf32(float c[4], unsigned a0, unsigned a1,
                                         unsigned a2, unsigned a3,
                                         unsigned b0, unsigned b1) {
    asm volatile(
        "mma.sync.aligned.m16n8k8.row.col.f32.tf32.tf32.f32 "
        "{%0,%1,%2,%3},{%4,%5,%6,%7},{%8,%9},{%0,%1,%2,%3};\n"
        : "+f"(c[0]), "+f"(c[1]), "+f"(c[2]), "+f"(c[3])
        : "r"(a0), "r"(a1), "r"(a2), "r"(a3), "r"(b0), "r"(b1));
}

// ---------------- prep: fuse + tf32-round fused q-weights ----------------
__global__ void prep_wq(const float* __restrict__ w_val, const float* __restrict__ w_off,
                        const float* __restrict__ w_attn, const float* __restrict__ b_val,
                        const float* __restrict__ b_off, const float* __restrict__ b_attn,
                        float* __restrict__ wq, float* __restrict__ bq) {
    int idx = blockIdx.x * blockDim.x + threadIdx.x;
    int row = idx >> 10, col = idx & 1023;
    float v;
    if      (col < 256) v = w_val [row * 256 + col];
    else if (col < 656) v = w_off [row * 400 + (col - 256)];
    else if (col < 856) v = w_attn[row * 200 + (col - 656)];
    else                v = 0.f;
    wq[idx] = tf32r(v);
    if (row == 0) {
        float b;
        if      (col < 256) b = b_val [col];
        else if (col < 656) b = b_off [col - 256];
        else if (col < 856) b = b_attn[col - 656];
        else                b = 0.f;
        bq[col] = b;
    }
}

// ---------------- LayerNorm (warp/row), tf32-rounded output ----------------
__global__ void ln_kernel(const float* __restrict__ x, const float* __restrict__ g,
                          const float* __restrict__ b, float* __restrict__ out) {
    int row  = blockIdx.x * blockDim.y + threadIdx.y;
    int lane = threadIdx.x;
    const float* xr = x + (size_t)row * CH;
    float v[8], s = 0.f, sq = 0.f;
#pragma unroll
    for (int i = 0; i < 8; i++) {
        v[i] = xr[lane + 32 * i];
        s += v[i]; sq += v[i] * v[i];
    }
#pragma unroll
    for (int o = 16; o > 0; o >>= 1) {
        s  += __shfl_xor_sync(0xffffffffu, s,  o);
        sq += __shfl_xor_sync(0xffffffffu, sq, o);
    }
    float mean = s * (1.f / 256.f);
    float var  = sq * (1.f / 256.f) - mean * mean;
    float rstd = rsqrtf(var + 1e-5f);
    float* outr = out + (size_t)row * CH;
#pragma unroll
    for (int i = 0; i < 8; i++) {
        int c = lane + 32 * i;
        outr[c] = tf32r((v[i] - mean) * rstd * g[c] + b[c]);
    }
}

// ---------------- TF32 tensor-core GEMM: C = A[M,K]@B[K,N] + bias ----------------
// CTA tile 256x128, warp tile 64x64, GBK=32, 3-stage cp.async pipeline.
// epi: 1 = bias+gelu+tf32round, 2 = bias+residual, 3 = proj (value->bf16, off/logit->f32)
#define ALD 36
#define BLD 132
#define A_ST (256 * ALD)   // floats per A stage
#define B_ST (32 * BLD)    // floats per B stage
#define GSMEM ((3 * (A_ST + B_ST)) * 4)

__global__ void __launch_bounds__(256, 1)
gemm_tf32(const float* __restrict__ A, const float* __restrict__ B,
          const float* __restrict__ bias, const float* __restrict__ R,
          float* __restrict__ C, __nv_bfloat16* __restrict__ valh,
          int M, int N, int K, int epi) {
    extern __shared__ float sm[];
    float* Asm = sm;
    float* Bsm = sm + 3 * A_ST;

    int tid = threadIdx.x, lane = tid & 31, warp = tid >> 5;
    int wr = warp >> 1, wc = warp & 1;
    int row0 = blockIdx.y * 256, col0 = blockIdx.x * 128;
    int gID = lane >> 2, tig = lane & 3;

    float acc[4][8][4] = {};
    int ntile = K / 32;

#define LOAD_STAGE(st, t)                                                     \
    {                                                                         \
        const float* Ag = A + (size_t)row0 * K + (t) * 32;                    \
        float* as = Asm + (st) * A_ST;                                        \
        _Pragma("unroll")                                                     \
        for (int i = 0; i < 8; i++) {                                         \
            int idx = tid + i * 256;                                          \
            int r = idx >> 3, c4 = (idx & 7) * 4;                             \
            cp16(&as[r * ALD + c4], Ag + (size_t)r * K + c4);                 \
        }                                                                     \
        const float* Bg = B + (size_t)((t) * 32) * N + col0;                  \
        float* bs = Bsm + (st) * B_ST;                                        \
        _Pragma("unroll")                                                     \
        for (int i = 0; i < 4; i++) {                                         \
            int idx = tid + i * 256;                                          \
            int k = idx >> 5, n4 = (idx & 31) * 4;                            \
            cp16(&bs[k * BLD + n4], Bg + (size_t)k * N + n4);                 \
        }                                                                     \
    }

    LOAD_STAGE(0, 0);
    asm volatile("cp.async.commit_group;\n");
    if (ntile > 1) LOAD_STAGE(1, 1);
    asm volatile("cp.async.commit_group;\n");

    for (int t = 0; t < ntile; t++) {
        __syncthreads();                    // stage (t+2)%3 free to overwrite
        if (t + 2 < ntile) LOAD_STAGE((t + 2) % 3, t + 2);
        asm volatile("cp.async.commit_group;\n");
        asm volatile("cp.async.wait_group 2;\n");
        __syncthreads();

        const float* as = Asm + (t % 3) * A_ST;
        const float* bs = Bsm + (t % 3) * B_ST;
#pragma unroll
        for (int ks = 0; ks < 4; ks++) {
            int k8 = ks * 8;
            unsigned af[4][4];
#pragma unroll
            for (int mt = 0; mt < 4; mt++) {
                int mrow = wr * 64 + mt * 16 + gID;
                af[mt][0] = __float_as_uint(as[mrow * ALD + k8 + tig]);
                af[mt][1] = __float_as_uint(as[(mrow + 8) * ALD + k8 + tig]);
                af[mt][2] = __float_as_uint(as[mrow * ALD + k8 + tig + 4]);
                af[mt][3] = __float_as_uint(as[(mrow + 8) * ALD + k8 + tig + 4]);
            }
#pragma unroll
            for (int nt = 0; nt < 8; nt++) {
                int ncol = wc * 64 + nt * 8 + gID;
                unsigned b0 = __float_as_uint(bs[(k8 + tig) * BLD + ncol]);
                unsigned b1 = __float_as_uint(bs[(k8 + tig + 4) * BLD + ncol]);
#pragma unroll
                for (int mt = 0; mt < 4; mt++)
                    mma_tf32(acc[mt][nt], af[mt][0], af[mt][1], af[mt][2], af[mt][3], b0, b1);
            }
        }
    }

#pragma unroll
    for (int mt = 0; mt < 4; mt++) {
#pragma unroll
        for (int nt = 0; nt < 8; nt++) {
            int row = row0 + wr * 64 + mt * 16 + gID;
            int col = col0 + wc * 64 + nt * 8 + tig * 2;
            float b0 = bias[col], b1 = bias[col + 1];
            float v0 = acc[mt][nt][0] + b0;
            float v1 = acc[mt][nt][1] + b1;
            float v2 = acc[mt][nt][2] + b0;
            float v3 = acc[mt][nt][3] + b1;
            if (epi == 1) {
                v0 = tf32r(0.5f * v0 * (1.f + erff(v0 * 0.70710678118654752440f)));
                v1 = tf32r(0.5f * v1 * (1.f + erff(v1 * 0.70710678118654752440f)));
                v2 = tf32r(0.5f * v2 * (1.f + erff(v2 * 0.70710678118654752440f)));
                v3 = tf32r(0.5f * v3 * (1.f + erff(v3 * 0.70710678118654752440f)));
            } else if (epi == 2) {
                const float* r0 = R + (size_t)row * N + col;
                const float* r1 = R + (size_t)(row + 8) * N + col;
                v0 += r0[0]; v1 += r0[1]; v2 += r1[0]; v3 += r1[1];
            }
            if (epi == 3) {
                if (col < 256) {
                    // value region -> bf16 table for deform gathers
                    *(__nv_bfloat162*)(valh + (size_t)row * CH + col) =
                        __floats2bfloat162_rn(v0, v1);
                    *(__nv_bfloat162*)(valh + (size_t)(row + 8) * CH + col) =
                        __floats2bfloat162_rn(v2, v3);
                } else if (col < 856) {
                    float* d0 = C + (size_t)row * N + col;
                    float* d1 = C + (size_t)(row + 8) * N + col;
                    d0[0] = v0; d0[1] = v1; d1[0] = v2; d1[1] = v3;
                }
            } else {
                float* d0 = C + (size_t)row * N + col;
                float* d1 = C + (size_t)(row + 8) * N + col;
                d0[0] = v0; d0[1] = v1; d1[0] = v2; d1[1] = v3;
            }
        }
    }
}

// ---------------- fused softmax + deformable bilinear attention (bf16 value) --------
__global__ void deform_kernel(const __nv_bfloat16* __restrict__ valh,
                              const float* __restrict__ proj,
                              const float* __restrict__ refp,
                              float* __restrict__ out) {
    int bq   = blockIdx.x;
    int n    = bq / LQ;
    int h    = threadIdx.y;
    int lane = threadIdx.x;

    const float* offr = proj + (size_t)bq * NQP + OFF_COL + h * (NP * 2);
    const float* logr = proj + (size_t)bq * NQP + LOG_COL + h * NP;
    float rx = refp[(size_t)bq * 2 + 0];
    float ry = refp[(size_t)bq * 2 + 1];

    float lg = (lane < NP) ? logr[lane] : -1e30f;
    float mx = lg;
#pragma unroll
    for (int o = 16; o > 0; o >>= 1) mx = fmaxf(mx, __shfl_xor_sync(0xffffffffu, mx, o));
    float e = (lane < NP) ? expf(lg - mx) : 0.f;
    float sum = e;
#pragma unroll
    for (int o = 16; o > 0; o >>= 1) sum += __shfl_xor_sync(0xffffffffu, sum, o);
    float awn = e / sum;

    const __nv_bfloat16* vb = valh + (size_t)n * LQ * CH + h * DH + lane;

    float acc = 0.f;
    for (int p = 0; p < NP; p++) {
        float ap = __shfl_sync(0xffffffffu, awn, p);
        float gx = fmaf(rx, 96.f, offr[2 * p]     - 0.5f);
        float gy = fmaf(ry, 96.f, offr[2 * p + 1] - 0.5f);
        float x0f = floorf(gx), y0f = floorf(gy);
        float fx = gx - x0f, fy = gy - y0f;
        int x0 = (int)x0f, y0 = (int)y0f;
        int x1 = x0 + 1,   y1 = y0 + 1;
        bool vx0 = (x0 >= 0) && (x0 <= 95);
        bool vx1 = (x1 >= 0) && (x1 <= 95);
        bool vy0 = (y0 >= 0) && (y0 <= 95);
        bool vy1 = (y1 >= 0) && (y1 <= 95);
        float w00 = (1.f - fx) * (1.f - fy) * ap;
        float w10 = fx * (1.f - fy) * ap;
        float w01 = (1.f - fx) * fy * ap;
        float w11 = fx * fy * ap;
        if (vx0 && vy0) acc = fmaf(w00, __bfloat162float(vb[(size_t)(y0 * 96 + x0) * CH]), acc);
        if (vx1 && vy0) acc = fmaf(w10, __bfloat162float(vb[(size_t)(y0 * 96 + x1) * CH]), acc);
        if (vx0 && vy1) acc = fmaf(w01, __bfloat162float(vb[(size_t)(y1 * 96 + x0) * CH]), acc);
        if (vx1 && vy1) acc = fmaf(w11, __bfloat162float(vb[(size_t)(y1 * 96 + x1) * CH]), acc);
    }
    out[(size_t)bq * CH + h * DH + lane] = tf32r(acc);
}

// ---------------- launch ----------------
extern "C" void kernel_launch(void* const* d_in, const int* in_sizes, int n_in,
                              void* d_out, int out_size) {
    const float* x      = (const float*)d_in[0];
    const float* refp   = (const float*)d_in[1];
    const float* ln1_g  = (const float*)d_in[4];
    const float* ln1_b  = (const float*)d_in[5];
    const float* w_off  = (const float*)d_in[6];
    const float* b_off  = (const float*)d_in[7];
    const float* w_attn = (const float*)d_in[8];
    const float* b_attn = (const float*)d_in[9];
    const float* w_val  = (const float*)d_in[10];
    const float* b_val  = (const float*)d_in[11];
    const float* w_out  = (const float*)d_in[12];
    const float* b_out  = (const float*)d_in[13];
    const float* ln2_g  = (const float*)d_in[14];
    const float* ln2_b  = (const float*)d_in[15];
    const float* w_fc1  = (const float*)d_in[16];
    const float* b_fc1  = (const float*)d_in[17];
    const float* w_fc2  = (const float*)d_in[18];
    const float* b_fc2  = (const float*)d_in[19];
    float* out = (float*)d_out;

    float *p_q, *p_proj, *p_attn, *p_x1, *p_y, *p_h1, *p_wq, *p_bq;
    __nv_bfloat16* p_valh;
    cudaGetSymbolAddress((void**)&p_q,    g_q);
    cudaGetSymbolAddress((void**)&p_proj, g_proj);
    cudaGetSymbolAddress((void**)&p_valh, g_valh);
    cudaGetSymbolAddress((void**)&p_attn, g_attn);
    cudaGetSymbolAddress((void**)&p_x1,   g_x1);
    cudaGetSymbolAddress((void**)&p_y,    g_y);
    cudaGetSymbolAddress((void**)&p_h1,   g_h1);
    cudaGetSymbolAddress((void**)&p_wq,   g_wq);
    cudaGetSymbolAddress((void**)&p_bq,   g_bq);

    static bool attr_done = false;
    if (!attr_done) {
        cudaFuncSetAttribute(gemm_tf32, cudaFuncAttributeMaxDynamicSharedMemorySize, GSMEM);
        attr_done = true;
    }

    prep_wq<<<CH * NQP / 256, 256>>>(w_val, w_off, w_attn, b_val, b_off, b_attn, p_wq, p_bq);

    dim3 lnBlock(32, 8);
    int  lnGrid = M_TOT / 8;

    // 1) LN1
    ln_kernel<<<lnGrid, lnBlock>>>(x, ln1_g, ln1_b, p_q);
    // 2) fused q-projection (value -> bf16 table, off/logit -> f32)
    gemm_tf32<<<dim3(NQP / 128, M_TOT / 256), 256, GSMEM>>>(
        p_q, p_wq, p_bq, nullptr, p_proj, p_valh, M_TOT, NQP, CH, 3);
    // 3) deform attention
    deform_kernel<<<M_TOT, dim3(32, 8)>>>(p_valh, p_proj, refp, p_attn);
    // 4) x1 = x + attn @ w_out + b_out   (w_out raw fp32; HMMA truncates)
    gemm_tf32<<<dim3(CH / 128, M_TOT / 256), 256, GSMEM>>>(
        p_attn, w_out, b_out, x, p_x1, nullptr, M_TOT, CH, CH, 2);
    // 5) LN2
    ln_kernel<<<lnGrid, lnBlock>>>(p_x1, ln2_g, ln2_b, p_y);
    // 6) h1 = gelu(y @ w_fc1 + b_fc1)
    gemm_tf32<<<dim3(HID / 128, M_TOT / 256), 256, GSMEM>>>(
        p_y, w_fc1, b_fc1, nullptr, p_h1, nullptr, M_TOT, HID, CH, 1);
    // 7) out = x1 + h1 @ w_fc2 + b_fc2
    gemm_tf32<<<dim3(CH / 128, M_TOT / 256), 256, GSMEM>>>(
        p_h1, w_fc2, b_fc2, p_x1, out, nullptr, M_TOT, CH, HID, 2);
}

// round 4
// speedup vs baseline: 2.5953x; 1.1147x over previous
#include <cuda_runtime.h>
#include <cuda_bf16.h>
#include <math.h>

#define LQ     9216
#define NBATCH 2
#define M_TOT  (NBATCH * LQ)     // 18432
#define CH     256
#define HEADS  8
#define NP     25
#define DH     32
#define HID    1024
#define NQP    1024              // [val 256 | off 400 | logit 200 | pad 168]
#define OFF_COL  256
#define LOG_COL  656

// ---------------- scratch ----------------
__device__ float g_q   [M_TOT * CH];
__device__ float g_proj[M_TOT * NQP];
__device__ float g_attn[M_TOT * CH];
__device__ float g_x1  [M_TOT * CH];
__device__ float g_y   [M_TOT * CH];
__device__ float g_h1  [M_TOT * HID];
__device__ float g_wq  [CH * NQP];
__device__ float g_bq  [NQP];

__device__ __forceinline__ float tf32r(float x) {
    unsigned u;
    asm("cvt.rna.tf32.f32 %0, %1;" : "=r"(u) : "f"(x));
    return __uint_as_float(u);
}

__device__ __forceinline__ void cp16(void* s, const void* g) {
    unsigned sa = (unsigned)__cvta_generic_to_shared(s);
    asm volatile("cp.async.cg.shared.global [%0], [%1], 16;\n" :: "r"(sa), "l"(g));
}

__device__ __forceinline__ void mma_tf32(float c[4], unsigned a0, unsigned a1,
                                         unsigned a2, unsigned a3,
                                         unsigned b0, unsigned b1) {
    asm volatile(
        "mma.sync.aligned.m16n8k8.row.col.f32.tf32.tf32.f32 "
        "{%0,%1,%2,%3},{%4,%5,%6,%7},{%8,%9},{%0,%1,%2,%3};\n"
        : "+f"(c[0]), "+f"(c[1]), "+f"(c[2]), "+f"(c[3])
        : "r"(a0), "r"(a1), "r"(a2), "r"(a3), "r"(b0), "r"(b1));
}

// ---------------- prep: fuse + tf32-round fused q-weights ----------------
__global__ void prep_wq(const float* __restrict__ w_val, const float* __restrict__ w_off,
                        const float* __restrict__ w_attn, const float* __restrict__ b_val,
                        const float* __restrict__ b_off, const float* __restrict__ b_attn,
                        float* __restrict__ wq, float* __restrict__ bq) {
    int idx = blockIdx.x * blockDim.x + threadIdx.x;
    int row = idx >> 10, col = idx & 1023;
    float v;
    if      (col < 256) v = w_val [row * 256 + col];
    else if (col < 656) v = w_off [row * 400 + (col - 256)];
    else if (col < 856) v = w_attn[row * 200 + (col - 656)];
    else                v = 0.f;
    wq[idx] = tf32r(v);
    if (row == 0) {
        float b;
        if      (col < 256) b = b_val [col];
        else if (col < 656) b = b_off [col - 256];
        else if (col < 856) b = b_attn[col - 656];
        else                b = 0.f;
        bq[col] = b;
    }
}

// ---------------- LayerNorm (warp/row), tf32-rounded output ----------------
__global__ void ln_kernel(const float* __restrict__ x, const float* __restrict__ g,
                          const float* __restrict__ b, float* __restrict__ out) {
    int row  = blockIdx.x * blockDim.y + threadIdx.y;
    int lane = threadIdx.x;
    const float* xr = x + (size_t)row * CH;
    float v[8], s = 0.f, sq = 0.f;
#pragma unroll
    for (int i = 0; i < 8; i++) {
        v[i] = xr[lane + 32 * i];
        s += v[i]; sq += v[i] * v[i];
    }
#pragma unroll
    for (int o = 16; o > 0; o >>= 1) {
        s  += __shfl_xor_sync(0xffffffffu, s,  o);
        sq += __shfl_xor_sync(0xffffffffu, sq, o);
    }
    float mean = s * (1.f / 256.f);
    float var  = sq * (1.f / 256.f) - mean * mean;
    float rstd = rsqrtf(var + 1e-5f);
    float* outr = out + (size_t)row * CH;
#pragma unroll
    for (int i = 0; i < 8; i++) {
        int c = lane + 32 * i;
        outr[c] = tf32r((v[i] - mean) * rstd * g[c] + b[c]);
    }
}

// ---------------- TF32 tensor-core GEMM ----------------
// epi: 0=bias, 1=bias+gelu+tf32round, 2=bias+residual, 3=proj(skip pad cols)
#define ALD 36
#define BLD 132
#define A_ST (256 * ALD)
#define B_ST (32 * BLD)
#define GSMEM ((3 * (A_ST + B_ST)) * 4)

__global__ void __launch_bounds__(256, 1)
gemm_tf32(const float* __restrict__ A, const float* __restrict__ B,
          const float* __restrict__ bias, const float* __restrict__ R,
          float* __restrict__ C, int M, int N, int K, int epi) {
    extern __shared__ float sm[];
    float* Asm = sm;
    float* Bsm = sm + 3 * A_ST;

    int tid = threadIdx.x, lane = tid & 31, warp = tid >> 5;
    int wr = warp >> 1, wc = warp & 1;
    int row0 = blockIdx.y * 256, col0 = blockIdx.x * 128;
    int gID = lane >> 2, tig = lane & 3;

    float acc[4][8][4] = {};
    int ntile = K / 32;

#define LOAD_STAGE(st, t)                                                     \
    {                                                                         \
        const float* Ag = A + (size_t)row0 * K + (t) * 32;                    \
        float* as = Asm + (st) * A_ST;                                        \
        _Pragma("unroll")                                                     \
        for (int i = 0; i < 8; i++) {                                         \
            int idx = tid + i * 256;                                          \
            int r = idx >> 3, c4 = (idx & 7) * 4;                             \
            cp16(&as[r * ALD + c4], Ag + (size_t)r * K + c4);                 \
        }                                                                     \
        const float* Bg = B + (size_t)((t) * 32) * N + col0;                  \
        float* bs = Bsm + (st) * B_ST;                                        \
        _Pragma("unroll")                                                     \
        for (int i = 0; i < 4; i++) {                                         \
            int idx = tid + i * 256;                                          \
            int k = idx >> 5, n4 = (idx & 31) * 4;                            \
            cp16(&bs[k * BLD + n4], Bg + (size_t)k * N + n4);                 \
        }                                                                     \
    }

    LOAD_STAGE(0, 0);
    asm volatile("cp.async.commit_group;\n");
    if (ntile > 1) LOAD_STAGE(1, 1);
    asm volatile("cp.async.commit_group;\n");

    for (int t = 0; t < ntile; t++) {
        __syncthreads();
        if (t + 2 < ntile) LOAD_STAGE((t + 2) % 3, t + 2);
        asm volatile("cp.async.commit_group;\n");
        asm volatile("cp.async.wait_group 2;\n");
        __syncthreads();

        const float* as = Asm + (t % 3) * A_ST;
        const float* bs = Bsm + (t % 3) * B_ST;
#pragma unroll
        for (int ks = 0; ks < 4; ks++) {
            int k8 = ks * 8;
            unsigned af[4][4];
#pragma unroll
            for (int mt = 0; mt < 4; mt++) {
                int mrow = wr * 64 + mt * 16 + gID;
                af[mt][0] = __float_as_uint(as[mrow * ALD + k8 + tig]);
                af[mt][1] = __float_as_uint(as[(mrow + 8) * ALD + k8 + tig]);
                af[mt][2] = __float_as_uint(as[mrow * ALD + k8 + tig + 4]);
                af[mt][3] = __float_as_uint(as[(mrow + 8) * ALD + k8 + tig + 4]);
            }
#pragma unroll
            for (int nt = 0; nt < 8; nt++) {
                int ncol = wc * 64 + nt * 8 + gID;
                unsigned b0 = __float_as_uint(bs[(k8 + tig) * BLD + ncol]);
                unsigned b1 = __float_as_uint(bs[(k8 + tig + 4) * BLD + ncol]);
#pragma unroll
                for (int mt = 0; mt < 4; mt++)
                    mma_tf32(acc[mt][nt], af[mt][0], af[mt][1], af[mt][2], af[mt][3], b0, b1);
            }
        }
    }

#pragma unroll
    for (int mt = 0; mt < 4; mt++) {
#pragma unroll
        for (int nt = 0; nt < 8; nt++) {
            int row = row0 + wr * 64 + mt * 16 + gID;
            int col = col0 + wc * 64 + nt * 8 + tig * 2;
            if (epi == 3 && col >= 856) continue;   // skip pad columns
            float b0 = bias[col], b1 = bias[col + 1];
            float v0 = acc[mt][nt][0] + b0;
            float v1 = acc[mt][nt][1] + b1;
            float v2 = acc[mt][nt][2] + b0;
            float v3 = acc[mt][nt][3] + b1;
            if (epi == 1) {
                v0 = tf32r(0.5f * v0 * (1.f + erff(v0 * 0.70710678118654752440f)));
                v1 = tf32r(0.5f * v1 * (1.f + erff(v1 * 0.70710678118654752440f)));
                v2 = tf32r(0.5f * v2 * (1.f + erff(v2 * 0.70710678118654752440f)));
                v3 = tf32r(0.5f * v3 * (1.f + erff(v3 * 0.70710678118654752440f)));
            } else if (epi == 2) {
                const float* r0 = R + (size_t)row * N + col;
                const float* r1 = R + (size_t)(row + 8) * N + col;
                v0 += r0[0]; v1 += r0[1]; v2 += r1[0]; v3 += r1[1];
            }
            float* d0 = C + (size_t)row * N + col;
            float* d1 = C + (size_t)(row + 8) * N + col;
            d0[0] = v0; d0[1] = v1; d1[0] = v2; d1[1] = v3;
        }
    }
}

// ---------------- fused softmax + deformable bilinear attention ----------------
// Warp per (query, head). Lane p<25 precomputes point p's 4 clamped corner byte
// offsets and softmax-premultiplied bilinear weights; gather loop broadcasts via
// shuffle. Values gathered fp32 straight from proj's value region.
__global__ void deform_kernel(const float* __restrict__ proj,
                              const float* __restrict__ refp,
                              float* __restrict__ out) {
    int bq   = blockIdx.x;
    int n    = bq / LQ;
    int h    = threadIdx.y;
    int lane = threadIdx.x;

    const float* rowp = proj + (size_t)bq * NQP;
    const float* logr = rowp + LOG_COL + h * NP;

    // softmax over 25 points (lanes 0..24)
    float lg = (lane < NP) ? logr[lane] : -1e30f;
    float mx = lg;
#pragma unroll
    for (int o = 16; o > 0; o >>= 1) mx = fmaxf(mx, __shfl_xor_sync(0xffffffffu, mx, o));
    float e = (lane < NP) ? expf(lg - mx) : 0.f;
    float sum = e;
#pragma unroll
    for (int o = 16; o > 0; o >>= 1) sum += __shfl_xor_sync(0xffffffffu, sum, o);
    float awn = e / sum;     // 0 for lanes >= 25

    // per-lane point precompute
    int   o00 = 0, o10 = 0, o01 = 0, o11 = 0;
    float w00 = 0.f, w10 = 0.f, w01 = 0.f, w11 = 0.f;
    if (lane < NP) {
        const float* offr = rowp + OFF_COL + h * (NP * 2);
        float rx = refp[(size_t)bq * 2 + 0];
        float ry = refp[(size_t)bq * 2 + 1];
        float gx = fmaf(rx, 96.f, offr[2 * lane]     - 0.5f);
        float gy = fmaf(ry, 96.f, offr[2 * lane + 1] - 0.5f);
        float x0f = floorf(gx), y0f = floorf(gy);
        float fx = gx - x0f, fy = gy - y0f;
        int x0 = (int)x0f, y0 = (int)y0f;
        int x1 = x0 + 1,   y1 = y0 + 1;
        bool vx0 = (x0 >= 0) && (x0 <= 95);
        bool vx1 = (x1 >= 0) && (x1 <= 95);
        bool vy0 = (y0 >= 0) && (y0 <= 95);
        bool vy1 = (y1 >= 0) && (y1 <= 95);
        int x0c = min(max(x0, 0), 95), x1c = min(max(x1, 0), 95);
        int y0c = min(max(y0, 0), 95), y1c = min(max(y1, 0), 95);
        w00 = (vx0 && vy0) ? (1.f - fx) * (1.f - fy) * awn : 0.f;
        w10 = (vx1 && vy0) ? fx * (1.f - fy) * awn : 0.f;
        w01 = (vx0 && vy1) ? (1.f - fx) * fy * awn : 0.f;
        w11 = (vx1 && vy1) ? fx * fy * awn : 0.f;
        o00 = (y0c * 96 + x0c) * (NQP * 4);    // byte offsets into proj rows
        o10 = (y0c * 96 + x1c) * (NQP * 4);
        o01 = (y1c * 96 + x0c) * (NQP * 4);
        o11 = (y1c * 96 + x1c) * (NQP * 4);
    }

    const char* vbase = (const char*)(proj + (size_t)n * LQ * NQP + h * DH + lane);

    float acc = 0.f;
#pragma unroll 5
    for (int p = 0; p < NP; p++) {
        int   b00 = __shfl_sync(0xffffffffu, o00, p);
        int   b10 = __shfl_sync(0xffffffffu, o10, p);
        int   b01 = __shfl_sync(0xffffffffu, o01, p);
        int   b11 = __shfl_sync(0xffffffffu, o11, p);
        float a00 = __shfl_sync(0xffffffffu, w00, p);
        float a10 = __shfl_sync(0xffffffffu, w10, p);
        float a01 = __shfl_sync(0xffffffffu, w01, p);
        float a11 = __shfl_sync(0xffffffffu, w11, p);
        acc = fmaf(a00, *(const float*)(vbase + b00), acc);
        acc = fmaf(a10, *(const float*)(vbase + b10), acc);
        acc = fmaf(a01, *(const float*)(vbase + b01), acc);
        acc = fmaf(a11, *(const float*)(vbase + b11), acc);
    }
    out[(size_t)bq * CH + h * DH + lane] = tf32r(acc);
}

// ---------------- launch ----------------
extern "C" void kernel_launch(void* const* d_in, const int* in_sizes, int n_in,
                              void* d_out, int out_size) {
    const float* x      = (const float*)d_in[0];
    const float* refp   = (const float*)d_in[1];
    const float* ln1_g  = (const float*)d_in[4];
    const float* ln1_b  = (const float*)d_in[5];
    const float* w_off  = (const float*)d_in[6];
    const float* b_off  = (const float*)d_in[7];
    const float* w_attn = (const float*)d_in[8];
    const float* b_attn = (const float*)d_in[9];
    const float* w_val  = (const float*)d_in[10];
    const float* b_val  = (const float*)d_in[11];
    const float* w_out  = (const float*)d_in[12];
    const float* b_out  = (const float*)d_in[13];
    const float* ln2_g  = (const float*)d_in[14];
    const float* ln2_b  = (const float*)d_in[15];
    const float* w_fc1  = (const float*)d_in[16];
    const float* b_fc1  = (const float*)d_in[17];
    const float* w_fc2  = (const float*)d_in[18];
    const float* b_fc2  = (const float*)d_in[19];
    float* out = (float*)d_out;

    float *p_q, *p_proj, *p_attn, *p_x1, *p_y, *p_h1, *p_wq, *p_bq;
    cudaGetSymbolAddress((void**)&p_q,    g_q);
    cudaGetSymbolAddress((void**)&p_proj, g_proj);
    cudaGetSymbolAddress((void**)&p_attn, g_attn);
    cudaGetSymbolAddress((void**)&p_x1,   g_x1);
    cudaGetSymbolAddress((void**)&p_y,    g_y);
    cudaGetSymbolAddress((void**)&p_h1,   g_h1);
    cudaGetSymbolAddress((void**)&p_wq,   g_wq);
    cudaGetSymbolAddress((void**)&p_bq,   g_bq);

    static bool attr_done = false;
    if (!attr_done) {
        cudaFuncSetAttribute(gemm_tf32, cudaFuncAttributeMaxDynamicSharedMemorySize, GSMEM);
        attr_done = true;
    }

    prep_wq<<<CH * NQP / 256, 256>>>(w_val, w_off, w_attn, b_val, b_off, b_attn, p_wq, p_bq);

    dim3 lnBlock(32, 8);
    int  lnGrid = M_TOT / 8;

    // 1) LN1
    ln_kernel<<<lnGrid, lnBlock>>>(x, ln1_g, ln1_b, p_q);
    // 2) fused q-projection: [val | off | logits]
    gemm_tf32<<<dim3(NQP / 128, M_TOT / 256), 256, GSMEM>>>(
        p_q, p_wq, p_bq, nullptr, p_proj, M_TOT, NQP, CH, 3);
    // 3) deform attention
    deform_kernel<<<M_TOT, dim3(32, 8)>>>(p_proj, refp, p_attn);
    // 4) x1 = x + attn @ w_out + b_out
    gemm_tf32<<<dim3(CH / 128, M_TOT / 256), 256, GSMEM>>>(
        p_attn, w_out, b_out, x, p_x1, M_TOT, CH, CH, 2);
    // 5) LN2
    ln_kernel<<<lnGrid, lnBlock>>>(p_x1, ln2_g, ln2_b, p_y);
    // 6) h1 = gelu(y @ w_fc1 + b_fc1)
    gemm_tf32<<<dim3(HID / 128, M_TOT / 256), 256, GSMEM>>>(
        p_y, w_fc1, b_fc1, nullptr, p_h1, M_TOT, HID, CH, 1);
    // 7) out = x1 + h1 @ w_fc2 + b_fc2
    gemm_tf32<<<dim3(CH / 128, M_TOT / 256), 256, GSMEM>>>(
        p_h1, w_fc2, b_fc2, p_x1, out, M_TOT, CH, HID, 2);
}

// round 5
// speedup vs baseline: 2.6537x; 1.0225x over previous
#include <cuda_runtime.h>
#include <cuda_bf16.h>
#include <math.h>

#define LQ     9216
#define NBATCH 2
#define M_TOT  (NBATCH * LQ)     // 18432
#define CH     256
#define HEADS  8
#define NP     25
#define DH     32
#define HID    1024
#define NQP    896               // [val 256 | off 400 | logit 200 | pad 40]
#define OFF_COL  256
#define LOG_COL  656

// ---------------- scratch ----------------
__device__ float g_q   [M_TOT * CH];
__device__ float g_proj[M_TOT * NQP];
__device__ float g_val [NBATCH * HEADS * LQ * DH + 64];  // [n,h,pix,ch] + pad
__device__ float g_attn[M_TOT * CH];
__device__ float g_x1  [M_TOT * CH];
__device__ float g_y   [M_TOT * CH];
__device__ float g_h1  [M_TOT * HID];
__device__ float g_wq  [CH * NQP];
__device__ float g_bq  [NQP];

__device__ __forceinline__ float tf32r(float x) {
    unsigned u;
    asm("cvt.rna.tf32.f32 %0, %1;" : "=r"(u) : "f"(x));
    return __uint_as_float(u);
}

__device__ __forceinline__ void cp16(void* s, const void* g) {
    unsigned sa = (unsigned)__cvta_generic_to_shared(s);
    asm volatile("cp.async.cg.shared.global [%0], [%1], 16;\n" :: "r"(sa), "l"(g));
}

__device__ __forceinline__ void mma_tf32(float c[4], unsigned a0, unsigned a1,
                                         unsigned a2, unsigned a3,
                                         unsigned b0, unsigned b1) {
    asm volatile(
        "mma.sync.aligned.m16n8k8.row.col.f32.tf32.tf32.f32 "
        "{%0,%1,%2,%3},{%4,%5,%6,%7},{%8,%9},{%0,%1,%2,%3};\n"
        : "+f"(c[0]), "+f"(c[1]), "+f"(c[2]), "+f"(c[3])
        : "r"(a0), "r"(a1), "r"(a2), "r"(a3), "r"(b0), "r"(b1));
}

// ---------------- prep: fuse + tf32-round fused q-weights ----------------
__global__ void prep_wq(const float* __restrict__ w_val, const float* __restrict__ w_off,
                        const float* __restrict__ w_attn, const float* __restrict__ b_val,
                        const float* __restrict__ b_off, const float* __restrict__ b_attn,
                        float* __restrict__ wq, float* __restrict__ bq) {
    int col = blockIdx.x * blockDim.x + threadIdx.x;   // 0..895
    int row = blockIdx.y;                              // 0..255
    float v;
    if      (col < 256) v = w_val [row * 256 + col];
    else if (col < 656) v = w_off [row * 400 + (col - 256)];
    else if (col < 856) v = w_attn[row * 200 + (col - 656)];
    else                v = 0.f;
    wq[row * NQP + col] = tf32r(v);
    if (row == 0) {
        float b;
        if      (col < 256) b = b_val [col];
        else if (col < 656) b = b_off [col - 256];
        else if (col < 856) b = b_attn[col - 656];
        else                b = 0.f;
        bq[col] = b;
    }
}

// ---------------- LayerNorm (warp/row), tf32-rounded output ----------------
__global__ void ln_kernel(const float* __restrict__ x, const float* __restrict__ g,
                          const float* __restrict__ b, float* __restrict__ out) {
    int row  = blockIdx.x * blockDim.y + threadIdx.y;
    int lane = threadIdx.x;
    const float* xr = x + (size_t)row * CH;
    float v[8], s = 0.f, sq = 0.f;
#pragma unroll
    for (int i = 0; i < 8; i++) {
        v[i] = xr[lane + 32 * i];
        s += v[i]; sq += v[i] * v[i];
    }
#pragma unroll
    for (int o = 16; o > 0; o >>= 1) {
        s  += __shfl_xor_sync(0xffffffffu, s,  o);
        sq += __shfl_xor_sync(0xffffffffu, sq, o);
    }
    float mean = s * (1.f / 256.f);
    float var  = sq * (1.f / 256.f) - mean * mean;
    float rstd = rsqrtf(var + 1e-5f);
    float* outr = out + (size_t)row * CH;
#pragma unroll
    for (int i = 0; i < 8; i++) {
        int c = lane + 32 * i;
        outr[c] = tf32r((v[i] - mean) * rstd * g[c] + b[c]);
    }
}

// ---------------- TF32 tensor-core GEMM ----------------
// epi: 0=bias, 1=bias+gelu+tf32round, 2=bias+residual,
//      3=proj: cols<256 -> value table [n,h,pix,ch]; 256..856 -> C; rest skipped
#define ALD 36
#define BLD 132
#define A_ST (256 * ALD)
#define B_ST (32 * BLD)
#define GSMEM ((3 * (A_ST + B_ST)) * 4)

__global__ void __launch_bounds__(256, 1)
gemm_tf32(const float* __restrict__ A, const float* __restrict__ B,
          const float* __restrict__ bias, const float* __restrict__ R,
          float* __restrict__ C, float* __restrict__ val,
          int M, int N, int K, int epi) {
    extern __shared__ float sm[];
    float* Asm = sm;
    float* Bsm = sm + 3 * A_ST;

    int tid = threadIdx.x, lane = tid & 31, warp = tid >> 5;
    int wr = warp >> 1, wc = warp & 1;
    int row0 = blockIdx.y * 256, col0 = blockIdx.x * 128;
    int gID = lane >> 2, tig = lane & 3;

    float acc[4][8][4] = {};
    int ntile = K / 32;

#define LOAD_STAGE(st, t)                                                     \
    {                                                                         \
        const float* Ag = A + (size_t)row0 * K + (t) * 32;                    \
        float* as = Asm + (st) * A_ST;                                        \
        _Pragma("unroll")                                                     \
        for (int i = 0; i < 8; i++) {                                         \
            int idx = tid + i * 256;                                          \
            int r = idx >> 3, c4 = (idx & 7) * 4;                             \
            cp16(&as[r * ALD + c4], Ag + (size_t)r * K + c4);                 \
        }                                                                     \
        const float* Bg = B + (size_t)((t) * 32) * N + col0;                  \
        float* bs = Bsm + (st) * B_ST;                                        \
        _Pragma("unroll")                                                     \
        for (int i = 0; i < 4; i++) {                                         \
            int idx = tid + i * 256;                                          \
            int k = idx >> 5, n4 = (idx & 31) * 4;                            \
            cp16(&bs[k * BLD + n4], Bg + (size_t)k * N + n4);                 \
        }                                                                     \
    }

    LOAD_STAGE(0, 0);
    asm volatile("cp.async.commit_group;\n");
    if (ntile > 1) LOAD_STAGE(1, 1);
    asm volatile("cp.async.commit_group;\n");

    for (int t = 0; t < ntile; t++) {
        __syncthreads();
        if (t + 2 < ntile) LOAD_STAGE((t + 2) % 3, t + 2);
        asm volatile("cp.async.commit_group;\n");
        asm volatile("cp.async.wait_group 2;\n");
        __syncthreads();

        const float* as = Asm + (t % 3) * A_ST;
        const float* bs = Bsm + (t % 3) * B_ST;
#pragma unroll
        for (int ks = 0; ks < 4; ks++) {
            int k8 = ks * 8;
            unsigned af[4][4];
#pragma unroll
            for (int mt = 0; mt < 4; mt++) {
                int mrow = wr * 64 + mt * 16 + gID;
                af[mt][0] = __float_as_uint(as[mrow * ALD + k8 + tig]);
                af[mt][1] = __float_as_uint(as[(mrow + 8) * ALD + k8 + tig]);
                af[mt][2] = __float_as_uint(as[mrow * ALD + k8 + tig + 4]);
                af[mt][3] = __float_as_uint(as[(mrow + 8) * ALD + k8 + tig + 4]);
            }
#pragma unroll
            for (int nt = 0; nt < 8; nt++) {
                int ncol = wc * 64 + nt * 8 + gID;
                unsigned b0 = __float_as_uint(bs[(k8 + tig) * BLD + ncol]);
                unsigned b1 = __float_as_uint(bs[(k8 + tig + 4) * BLD + ncol]);
#pragma unroll
                for (int mt = 0; mt < 4; mt++)
                    mma_tf32(acc[mt][nt], af[mt][0], af[mt][1], af[mt][2], af[mt][3], b0, b1);
            }
        }
    }

#pragma unroll
    for (int mt = 0; mt < 4; mt++) {
#pragma unroll
        for (int nt = 0; nt < 8; nt++) {
            int row = row0 + wr * 64 + mt * 16 + gID;
            int col = col0 + wc * 64 + nt * 8 + tig * 2;
            if (epi == 3 && col >= 856) continue;
            float b0 = bias[col], b1 = bias[col + 1];
            float v0 = acc[mt][nt][0] + b0;
            float v1 = acc[mt][nt][1] + b1;
            float v2 = acc[mt][nt][2] + b0;
            float v3 = acc[mt][nt][3] + b1;
            if (epi == 1) {
                v0 = tf32r(0.5f * v0 * (1.f + erff(v0 * 0.70710678118654752440f)));
                v1 = tf32r(0.5f * v1 * (1.f + erff(v1 * 0.70710678118654752440f)));
                v2 = tf32r(0.5f * v2 * (1.f + erff(v2 * 0.70710678118654752440f)));
                v3 = tf32r(0.5f * v3 * (1.f + erff(v3 * 0.70710678118654752440f)));
            } else if (epi == 2) {
                const float* r0 = R + (size_t)row * N + col;
                const float* r1 = R + (size_t)(row + 8) * N + col;
                v0 += r0[0]; v1 += r0[1]; v2 += r1[0]; v3 += r1[1];
            }
            if (epi == 3 && col < 256) {
                // value -> [n, h, pix, 32ch] layout (128B per pixel*head)
                int h  = col >> 5, dh = col & 31;
                int n_ = row / LQ, pix = row - n_ * LQ;
                float* d0 = val + ((size_t)(n_ * HEADS + h) * LQ + pix) * DH + dh;
                float* d1 = d0 + (size_t)8 * DH;   // row+8 -> pix+8
                *(float2*)d0 = make_float2(v0, v1);
                *(float2*)d1 = make_float2(v2, v3);
            } else {
                float* d0 = C + (size_t)row * N + col;
                float* d1 = C + (size_t)(row + 8) * N + col;
                d0[0] = v0; d0[1] = v1; d1[0] = v2; d1[1] = v3;
            }
        }
    }
}

// ---------------- fused softmax + deformable bilinear attention ----------------
// Warp per (query, head). Value table [n,h,pix,32ch]: a 2x2 bilinear patch is two
// contiguous 256B rows -> one LDG.64 per lane per row (lanes 0-15 = pixel x,
// lanes 16-31 = pixel x+1). Lane p<25 precomputes offsets + zeroed-edge weights.
__global__ void deform_kernel(const float* __restrict__ val,
                              const float* __restrict__ proj,
                              const float* __restrict__ refp,
                              float* __restrict__ out) {
    int bq   = blockIdx.x;
    int n    = bq / LQ;
    int h    = threadIdx.y;
    int lane = threadIdx.x;

    const float* rowp = proj + (size_t)bq * NQP;
    const float* logr = rowp + LOG_COL + h * NP;

    // softmax over 25 points (lanes 0..24)
    float lg = (lane < NP) ? logr[lane] : -1e30f;
    float mx = lg;
#pragma unroll
    for (int o = 16; o > 0; o >>= 1) mx = fmaxf(mx, __shfl_xor_sync(0xffffffffu, mx, o));
    float e = (lane < NP) ? expf(lg - mx) : 0.f;
    float sum = e;
#pragma unroll
    for (int o = 16; o > 0; o >>= 1) sum += __shfl_xor_sync(0xffffffffu, sum, o);
    float awn = e / sum;

    // per-lane point precompute
    int   o0 = 0, o1 = 0;
    float w0lo = 0.f, w0hi = 0.f, w1lo = 0.f, w1hi = 0.f;
    if (lane < NP) {
        const float* offr = rowp + OFF_COL + h * (NP * 2);
        float rx = refp[(size_t)bq * 2 + 0];
        float ry = refp[(size_t)bq * 2 + 1];
        float gx = fmaf(rx, 96.f, offr[2 * lane]     - 0.5f);
        float gy = fmaf(ry, 96.f, offr[2 * lane + 1] - 0.5f);
        float x0f = floorf(gx), y0f = floorf(gy);
        float fx = gx - x0f, fy = gy - y0f;
        int x0 = (int)x0f, y0 = (int)y0f;
        int x1 = x0 + 1,   y1 = y0 + 1;
        int px = min(max(x0, 0), 95);
        float wx0 = (x0 >= 0 && x0 < 96) ? (1.f - fx) : 0.f;
        float wx1 = (x1 >= 0 && x1 < 96) ? fx : 0.f;
        bool at0 = (px == x0);
        float wlo = at0 ? wx0 : wx1;     // weight for patch pixel px
        float whi = at0 ? wx1 : 0.f;     // weight for patch pixel px+1
        float wy0 = (y0 >= 0 && y0 < 96) ? (1.f - fy) : 0.f;
        float wy1 = (y1 >= 0 && y1 < 96) ? fy : 0.f;
        int ry0 = min(max(y0, 0), 95);
        int ry1 = min(max(y1, 0), 95);
        o0 = (ry0 * 96 + px) * (DH * 4);     // byte offset of patch row 0
        o1 = (ry1 * 96 + px) * (DH * 4);
        w0lo = wy0 * wlo * awn;  w0hi = wy0 * whi * awn;
        w1lo = wy1 * wlo * awn;  w1hi = wy1 * whi * awn;
    }

    // lane*8 bytes: lanes 0-15 cover pixel px channels, 16-31 cover pixel px+1
    const char* vb = (const char*)(val + (size_t)(n * HEADS + h) * LQ * DH) + lane * 8;
    bool lo = (lane < 16);

    float accx = 0.f, accy = 0.f;
#pragma unroll 5
    for (int p = 0; p < NP; p++) {
        int   b0  = __shfl_sync(0xffffffffu, o0, p);
        int   b1  = __shfl_sync(0xffffffffu, o1, p);
        float s0l = __shfl_sync(0xffffffffu, w0lo, p);
        float s0h = __shfl_sync(0xffffffffu, w0hi, p);
        float s1l = __shfl_sync(0xffffffffu, w1lo, p);
        float s1h = __shfl_sync(0xffffffffu, w1hi, p);
        float a0 = lo ? s0l : s0h;
        float a1 = lo ? s1l : s1h;
        float2 v0 = *(const float2*)(vb + b0);
        float2 v1 = *(const float2*)(vb + b1);
        accx = fmaf(a0, v0.x, accx);
        accy = fmaf(a0, v0.y, accy);
        accx = fmaf(a1, v1.x, accx);
        accy = fmaf(a1, v1.y, accy);
    }
    accx += __shfl_xor_sync(0xffffffffu, accx, 16);
    accy += __shfl_xor_sync(0xffffffffu, accy, 16);

    if (lo) {
        float2 r = make_float2(tf32r(accx), tf32r(accy));
        *(float2*)(out + (size_t)bq * CH + h * DH + lane * 2) = r;
    }
}

// ---------------- launch ----------------
extern "C" void kernel_launch(void* const* d_in, const int* in_sizes, int n_in,
                              void* d_out, int out_size) {
    const float* x      = (const float*)d_in[0];
    const float* refp   = (const float*)d_in[1];
    const float* ln1_g  = (const float*)d_in[4];
    const float* ln1_b  = (const float*)d_in[5];
    const float* w_off  = (const float*)d_in[6];
    const float* b_off  = (const float*)d_in[7];
    const float* w_attn = (const float*)d_in[8];
    const float* b_attn = (const float*)d_in[9];
    const float* w_val  = (const float*)d_in[10];
    const float* b_val  = (const float*)d_in[11];
    const float* w_out  = (const float*)d_in[12];
    const float* b_out  = (const float*)d_in[13];
    const float* ln2_g  = (const float*)d_in[14];
    const float* ln2_b  = (const float*)d_in[15];
    const float* w_fc1  = (const float*)d_in[16];
    const float* b_fc1  = (const float*)d_in[17];
    const float* w_fc2  = (const float*)d_in[18];
    const float* b_fc2  = (const float*)d_in[19];
    float* out = (float*)d_out;

    float *p_q, *p_proj, *p_val, *p_attn, *p_x1, *p_y, *p_h1, *p_wq, *p_bq;
    cudaGetSymbolAddress((void**)&p_q,    g_q);
    cudaGetSymbolAddress((void**)&p_proj, g_proj);
    cudaGetSymbolAddress((void**)&p_val,  g_val);
    cudaGetSymbolAddress((void**)&p_attn, g_attn);
    cudaGetSymbolAddress((void**)&p_x1,   g_x1);
    cudaGetSymbolAddress((void**)&p_y,    g_y);
    cudaGetSymbolAddress((void**)&p_h1,   g_h1);
    cudaGetSymbolAddress((void**)&p_wq,   g_wq);
    cudaGetSymbolAddress((void**)&p_bq,   g_bq);

    static bool attr_done = false;
    if (!attr_done) {
        cudaFuncSetAttribute(gemm_tf32, cudaFuncAttributeMaxDynamicSharedMemorySize, GSMEM);
        attr_done = true;
    }

    prep_wq<<<dim3(NQP / 128, CH), 128>>>(w_val, w_off, w_attn, b_val, b_off, b_attn, p_wq, p_bq);

    dim3 lnBlock(32, 8);
    int  lnGrid = M_TOT / 8;

    // 1) LN1
    ln_kernel<<<lnGrid, lnBlock>>>(x, ln1_g, ln1_b, p_q);
    // 2) fused q-projection: [val | off | logits]
    gemm_tf32<<<dim3(NQP / 128, M_TOT / 256), 256, GSMEM>>>(
        p_q, p_wq, p_bq, nullptr, p_proj, p_val, M_TOT, NQP, CH, 3);
    // 3) deform attention
    deform_kernel<<<M_TOT, dim3(32, 8)>>>(p_val, p_proj, refp, p_attn);
    // 4) x1 = x + attn @ w_out + b_out
    gemm_tf32<<<dim3(CH / 128, M_TOT / 256), 256, GSMEM>>>(
        p_attn, w_out, b_out, x, p_x1, nullptr, M_TOT, CH, CH, 2);
    // 5) LN2
    ln_kernel<<<lnGrid, lnBlock>>>(p_x1, ln2_g, ln2_b, p_y);
    // 6) h1 = gelu(y @ w_fc1 + b_fc1)
    gemm_tf32<<<dim3(HID / 128, M_TOT / 256), 256, GSMEM>>>(
        p_y, w_fc1, b_fc1, nullptr, p_h1, nullptr, M_TOT, HID, CH, 1);
    // 7) out = x1 + h1 @ w_fc2 + b_fc2
    gemm_tf32<<<dim3(CH / 128, M_TOT / 256), 256, GSMEM>>>(
        p_h1, w_fc2, b_fc2, p_x1, out, nullptr, M_TOT, CH, HID, 2);
}

// round 6
// speedup vs baseline: 2.7308x; 1.0291x over previous
#include <cuda_runtime.h>
#include <cuda_bf16.h>
#include <math.h>

#define LQ     9216
#define NBATCH 2
#define M_TOT  (NBATCH * LQ)     // 18432
#define CH     256
#define HEADS  8
#define NP     25
#define DH     32
#define HID    1024
#define NQP    896               // [val 256 | off 400 | logit 200 | pad 40]
#define OFF_COL  256
#define LOG_COL  656

// ---------------- scratch ----------------
__device__ float         g_q   [M_TOT * CH];
__device__ float         g_proj[M_TOT * NQP];
__device__ __nv_bfloat16 g_valh[NBATCH * HEADS * LQ * DH + 64];  // [n,h,pix,ch] bf16 + pad
__device__ float         g_attn[M_TOT * CH];
__device__ float         g_x1  [M_TOT * CH];
__device__ float         g_y   [M_TOT * CH];
__device__ float         g_h1  [M_TOT * HID];
__device__ float         g_wq  [CH * NQP];
__device__ float         g_bq  [NQP];

__device__ __forceinline__ float tf32r(float x) {
    unsigned u;
    asm("cvt.rna.tf32.f32 %0, %1;" : "=r"(u) : "f"(x));
    return __uint_as_float(u);
}

__device__ __forceinline__ void cp16(void* s, const void* g) {
    unsigned sa = (unsigned)__cvta_generic_to_shared(s);
    asm volatile("cp.async.cg.shared.global [%0], [%1], 16;\n" :: "r"(sa), "l"(g));
}

__device__ __forceinline__ void mma_tf32(float c[4], unsigned a0, unsigned a1,
                                         unsigned a2, unsigned a3,
                                         unsigned b0, unsigned b1) {
    asm volatile(
        "mma.sync.aligned.m16n8k8.row.col.f32.tf32.tf32.f32 "
        "{%0,%1,%2,%3},{%4,%5,%6,%7},{%8,%9},{%0,%1,%2,%3};\n"
        : "+f"(c[0]), "+f"(c[1]), "+f"(c[2]), "+f"(c[3])
        : "r"(a0), "r"(a1), "r"(a2), "r"(a3), "r"(b0), "r"(b1));
}

// ---------------- prep: fuse + tf32-round fused q-weights ----------------
__global__ void prep_wq(const float* __restrict__ w_val, const float* __restrict__ w_off,
                        const float* __restrict__ w_attn, const float* __restrict__ b_val,
                        const float* __restrict__ b_off, const float* __restrict__ b_attn,
                        float* __restrict__ wq, float* __restrict__ bq) {
    int col = blockIdx.x * blockDim.x + threadIdx.x;   // 0..895
    int row = blockIdx.y;                              // 0..255
    float v;
    if      (col < 256) v = w_val [row * 256 + col];
    else if (col < 656) v = w_off [row * 400 + (col - 256)];
    else if (col < 856) v = w_attn[row * 200 + (col - 656)];
    else                v = 0.f;
    wq[row * NQP + col] = tf32r(v);
    if (row == 0) {
        float b;
        if      (col < 256) b = b_val [col];
        else if (col < 656) b = b_off [col - 256];
        else if (col < 856) b = b_attn[col - 656];
        else                b = 0.f;
        bq[col] = b;
    }
}

// ---------------- LayerNorm (warp/row), tf32-rounded output ----------------
__global__ void ln_kernel(const float* __restrict__ x, const float* __restrict__ g,
                          const float* __restrict__ b, float* __restrict__ out) {
    int row  = blockIdx.x * blockDim.y + threadIdx.y;
    int lane = threadIdx.x;
    const float* xr = x + (size_t)row * CH;
    float v[8], s = 0.f, sq = 0.f;
#pragma unroll
    for (int i = 0; i < 8; i++) {
        v[i] = xr[lane + 32 * i];
        s += v[i]; sq += v[i] * v[i];
    }
#pragma unroll
    for (int o = 16; o > 0; o >>= 1) {
        s  += __shfl_xor_sync(0xffffffffu, s,  o);
        sq += __shfl_xor_sync(0xffffffffu, sq, o);
    }
    float mean = s * (1.f / 256.f);
    float var  = sq * (1.f / 256.f) - mean * mean;
    float rstd = rsqrtf(var + 1e-5f);
    float* outr = out + (size_t)row * CH;
#pragma unroll
    for (int i = 0; i < 8; i++) {
        int c = lane + 32 * i;
        outr[c] = tf32r((v[i] - mean) * rstd * g[c] + b[c]);
    }
}

// ---------------- TF32 tensor-core GEMM ----------------
// epi: 0=bias, 1=bias+gelu+tf32round, 2=bias+residual,
//      3=proj: cols<256 -> bf16 value table [n,h,pix,ch]; 256..856 -> C; rest skipped
#define ALD 36
#define BLD 132
#define A_ST (256 * ALD)
#define B_ST (32 * BLD)
#define GSMEM ((3 * (A_ST + B_ST)) * 4)

__global__ void __launch_bounds__(256, 1)
gemm_tf32(const float* __restrict__ A, const float* __restrict__ B,
          const float* __restrict__ bias, const float* __restrict__ R,
          float* __restrict__ C, __nv_bfloat16* __restrict__ valh,
          int M, int N, int K, int epi) {
    extern __shared__ float sm[];
    float* Asm = sm;
    float* Bsm = sm + 3 * A_ST;

    int tid = threadIdx.x, lane = tid & 31, warp = tid >> 5;
    int wr = warp >> 1, wc = warp & 1;
    int row0 = blockIdx.y * 256, col0 = blockIdx.x * 128;
    int gID = lane >> 2, tig = lane & 3;

    float acc[4][8][4] = {};
    int ntile = K / 32;

#define LOAD_STAGE(st, t)                                                     \
    {                                                                         \
        const float* Ag = A + (size_t)row0 * K + (t) * 32;                    \
        float* as = Asm + (st) * A_ST;                                        \
        _Pragma("unroll")                                                     \
        for (int i = 0; i < 8; i++) {                                         \
            int idx = tid + i * 256;                                          \
            int r = idx >> 3, c4 = (idx & 7) * 4;                             \
            cp16(&as[r * ALD + c4], Ag + (size_t)r * K + c4);                 \
        }                                                                     \
        const float* Bg = B + (size_t)((t) * 32) * N + col0;                  \
        float* bs = Bsm + (st) * B_ST;                                        \
        _Pragma("unroll")                                                     \
        for (int i = 0; i < 4; i++) {                                         \
            int idx = tid + i * 256;                                          \
            int k = idx >> 5, n4 = (idx & 31) * 4;                            \
            cp16(&bs[k * BLD + n4], Bg + (size_t)k * N + n4);                 \
        }                                                                     \
    }

    LOAD_STAGE(0, 0);
    asm volatile("cp.async.commit_group;\n");
    if (ntile > 1) LOAD_STAGE(1, 1);
    asm volatile("cp.async.commit_group;\n");

    for (int t = 0; t < ntile; t++) {
        __syncthreads();
        if (t + 2 < ntile) LOAD_STAGE((t + 2) % 3, t + 2);
        asm volatile("cp.async.commit_group;\n");
        asm volatile("cp.async.wait_group 2;\n");
        __syncthreads();

        const float* as = Asm + (t % 3) * A_ST;
        const float* bs = Bsm + (t % 3) * B_ST;
#pragma unroll
        for (int ks = 0; ks < 4; ks++) {
            int k8 = ks * 8;
            unsigned af[4][4];
#pragma unroll
            for (int mt = 0; mt < 4; mt++) {
                int mrow = wr * 64 + mt * 16 + gID;
                af[mt][0] = __float_as_uint(as[mrow * ALD + k8 + tig]);
                af[mt][1] = __float_as_uint(as[(mrow + 8) * ALD + k8 + tig]);
                af[mt][2] = __float_as_uint(as[mrow * ALD + k8 + tig + 4]);
                af[mt][3] = __float_as_uint(as[(mrow + 8) * ALD + k8 + tig + 4]);
            }
#pragma unroll
            for (int nt = 0; nt < 8; nt++) {
                int ncol = wc * 64 + nt * 8 + gID;
                unsigned b0 = __float_as_uint(bs[(k8 + tig) * BLD + ncol]);
                unsigned b1 = __float_as_uint(bs[(k8 + tig + 4) * BLD + ncol]);
#pragma unroll
                for (int mt = 0; mt < 4; mt++)
                    mma_tf32(acc[mt][nt], af[mt][0], af[mt][1], af[mt][2], af[mt][3], b0, b1);
            }
        }
    }

#pragma unroll
    for (int mt = 0; mt < 4; mt++) {
#pragma unroll
        for (int nt = 0; nt < 8; nt++) {
            int row = row0 + wr * 64 + mt * 16 + gID;
            int col = col0 + wc * 64 + nt * 8 + tig * 2;
            if (epi == 3 && col >= 856) continue;
            float b0 = bias[col], b1 = bias[col + 1];
            float v0 = acc[mt][nt][0] + b0;
            float v1 = acc[mt][nt][1] + b1;
            float v2 = acc[mt][nt][2] + b0;
            float v3 = acc[mt][nt][3] + b1;
            if (epi == 1) {
                v0 = tf32r(0.5f * v0 * (1.f + erff(v0 * 0.70710678118654752440f)));
                v1 = tf32r(0.5f * v1 * (1.f + erff(v1 * 0.70710678118654752440f)));
                v2 = tf32r(0.5f * v2 * (1.f + erff(v2 * 0.70710678118654752440f)));
                v3 = tf32r(0.5f * v3 * (1.f + erff(v3 * 0.70710678118654752440f)));
            } else if (epi == 2) {
                const float* r0 = R + (size_t)row * N + col;
                const float* r1 = R + (size_t)(row + 8) * N + col;
                v0 += r0[0]; v1 += r0[1]; v2 += r1[0]; v3 += r1[1];
            }
            if (epi == 3 && col < 256) {
                // value -> bf16 [n, h, pix, 32ch] layout (64B per pixel*head)
                int h  = col >> 5, dh = col & 31;
                int n_ = row / LQ, pix = row - n_ * LQ;
                __nv_bfloat16* d0 = valh + ((size_t)(n_ * HEADS + h) * LQ + pix) * DH + dh;
                __nv_bfloat16* d1 = d0 + (size_t)8 * DH;   // row+8 -> pix+8
                *(__nv_bfloat162*)d0 = __floats2bfloat162_rn(v0, v1);
                *(__nv_bfloat162*)d1 = __floats2bfloat162_rn(v2, v3);
            } else {
                float* d0 = C + (size_t)row * N + col;
                float* d1 = C + (size_t)(row + 8) * N + col;
                d0[0] = v0; d0[1] = v1; d1[0] = v2; d1[1] = v3;
            }
        }
    }
}

// ---------------- fused softmax + deformable bilinear attention ----------------
// Warp per (query, head). bf16 value table [n,h,pix,32ch] (64B/pixel): a bilinear
// patch row (2 x-pixels) = 128 contiguous bytes -> ONE coalesced LDG.32 per lane:
// lanes 0-15 = pixel px channels (2/lane), lanes 16-31 = pixel px+1 channels.
__global__ void deform_kernel(const __nv_bfloat16* __restrict__ valh,
                              const float* __restrict__ proj,
                              const float* __restrict__ refp,
                              float* __restrict__ out) {
    int bq   = blockIdx.x;
    int n    = bq / LQ;
    int h    = threadIdx.y;
    int lane = threadIdx.x;

    const float* rowp = proj + (size_t)bq * NQP;
    const float* logr = rowp + LOG_COL + h * NP;

    // softmax over 25 points (lanes 0..24)
    float lg = (lane < NP) ? logr[lane] : -1e30f;
    float mx = lg;
#pragma unroll
    for (int o = 16; o > 0; o >>= 1) mx = fmaxf(mx, __shfl_xor_sync(0xffffffffu, mx, o));
    float e = (lane < NP) ? expf(lg - mx) : 0.f;
    float sum = e;
#pragma unroll
    for (int o = 16; o > 0; o >>= 1) sum += __shfl_xor_sync(0xffffffffu, sum, o);
    float awn = e / sum;

    // per-lane point precompute
    int   o0 = 0, o1 = 0;
    float w0lo = 0.f, w0hi = 0.f, w1lo = 0.f, w1hi = 0.f;
    if (lane < NP) {
        const float* offr = rowp + OFF_COL + h * (NP * 2);
        float rx = refp[(size_t)bq * 2 + 0];
        float ry = refp[(size_t)bq * 2 + 1];
        float gx = fmaf(rx, 96.f, offr[2 * lane]     - 0.5f);
        float gy = fmaf(ry, 96.f, offr[2 * lane + 1] - 0.5f);
        float x0f = floorf(gx), y0f = floorf(gy);
        float fx = gx - x0f, fy = gy - y0f;
        int x0 = (int)x0f, y0 = (int)y0f;
        int x1 = x0 + 1,   y1 = y0 + 1;
        int px = min(max(x0, 0), 95);
        float wx0 = (x0 >= 0 && x0 < 96) ? (1.f - fx) : 0.f;
        float wx1 = (x1 >= 0 && x1 < 96) ? fx : 0.f;
        bool at0 = (px == x0);
        float wlo = at0 ? wx0 : wx1;     // weight for patch pixel px
        float whi = at0 ? wx1 : 0.f;     // weight for patch pixel px+1
        float wy0 = (y0 >= 0 && y0 < 96) ? (1.f - fy) : 0.f;
        float wy1 = (y1 >= 0 && y1 < 96) ? fy : 0.f;
        int ry0 = min(max(y0, 0), 95);
        int ry1 = min(max(y1, 0), 95);
        o0 = (ry0 * 96 + px) * (DH * 2);     // byte offset of patch row 0 (bf16)
        o1 = (ry1 * 96 + px) * (DH * 2);
        w0lo = wy0 * wlo * awn;  w0hi = wy0 * whi * awn;
        w1lo = wy1 * wlo * awn;  w1hi = wy1 * whi * awn;
    }

    // lane*4 bytes: lanes 0-15 -> pixel px (2 ch/lane), lanes 16-31 -> pixel px+1
    const char* vb = (const char*)(valh + (size_t)(n * HEADS + h) * LQ * DH) + lane * 4;
    bool lo = (lane < 16);

    float accx = 0.f, accy = 0.f;
#pragma unroll 5
    for (int p = 0; p < NP; p++) {
        int   b0  = __shfl_sync(0xffffffffu, o0, p);
        int   b1  = __shfl_sync(0xffffffffu, o1, p);
        float s0l = __shfl_sync(0xffffffffu, w0lo, p);
        float s0h = __shfl_sync(0xffffffffu, w0hi, p);
        float s1l = __shfl_sync(0xffffffffu, w1lo, p);
        float s1h = __shfl_sync(0xffffffffu, w1hi, p);
        float a0 = lo ? s0l : s0h;
        float a1 = lo ? s1l : s1h;
        float2 v0 = __bfloat1622float2(*(const __nv_bfloat162*)(vb + b0));
        float2 v1 = __bfloat1622float2(*(const __nv_bfloat162*)(vb + b1));
        accx = fmaf(a0, v0.x, accx);
        accy = fmaf(a0, v0.y, accy);
        accx = fmaf(a1, v1.x, accx);
        accy = fmaf(a1, v1.y, accy);
    }
    accx += __shfl_xor_sync(0xffffffffu, accx, 16);
    accy += __shfl_xor_sync(0xffffffffu, accy, 16);

    if (lo) {
        float2 r = make_float2(tf32r(accx), tf32r(accy));
        *(float2*)(out + (size_t)bq * CH + h * DH + lane * 2) = r;
    }
}

// ---------------- launch ----------------
extern "C" void kernel_launch(void* const* d_in, const int* in_sizes, int n_in,
                              void* d_out, int out_size) {
    const float* x      = (const float*)d_in[0];
    const float* refp   = (const float*)d_in[1];
    const float* ln1_g  = (const float*)d_in[4];
    const float* ln1_b  = (const float*)d_in[5];
    const float* w_off  = (const float*)d_in[6];
    const float* b_off  = (const float*)d_in[7];
    const float* w_attn = (const float*)d_in[8];
    const float* b_attn = (const float*)d_in[9];
    const float* w_val  = (const float*)d_in[10];
    const float* b_val  = (const float*)d_in[11];
    const float* w_out  = (const float*)d_in[12];
    const float* b_out  = (const float*)d_in[13];
    const float* ln2_g  = (const float*)d_in[14];
    const float* ln2_b  = (const float*)d_in[15];
    const float* w_fc1  = (const float*)d_in[16];
    const float* b_fc1  = (const float*)d_in[17];
    const float* w_fc2  = (const float*)d_in[18];
    const float* b_fc2  = (const float*)d_in[19];
    float* out = (float*)d_out;

    float *p_q, *p_proj, *p_attn, *p_x1, *p_y, *p_h1, *p_wq, *p_bq;
    __nv_bfloat16* p_valh;
    cudaGetSymbolAddress((void**)&p_q,    g_q);
    cudaGetSymbolAddress((void**)&p_proj, g_proj);
    cudaGetSymbolAddress((void**)&p_valh, g_valh);
    cudaGetSymbolAddress((void**)&p_attn, g_attn);
    cudaGetSymbolAddress((void**)&p_x1,   g_x1);
    cudaGetSymbolAddress((void**)&p_y,    g_y);
    cudaGetSymbolAddress((void**)&p_h1,   g_h1);
    cudaGetSymbolAddress((void**)&p_wq,   g_wq);
    cudaGetSymbolAddress((void**)&p_bq,   g_bq);

    static bool attr_done = false;
    if (!attr_done) {
        cudaFuncSetAttribute(gemm_tf32, cudaFuncAttributeMaxDynamicSharedMemorySize, GSMEM);
        attr_done = true;
    }

    prep_wq<<<dim3(NQP / 128, CH), 128>>>(w_val, w_off, w_attn, b_val, b_off, b_attn, p_wq, p_bq);

    dim3 lnBlock(32, 8);
    int  lnGrid = M_TOT / 8;

    // 1) LN1
    ln_kernel<<<lnGrid, lnBlock>>>(x, ln1_g, ln1_b, p_q);
    // 2) fused q-projection: [val | off | logits]
    gemm_tf32<<<dim3(NQP / 128, M_TOT / 256), 256, GSMEM>>>(
        p_q, p_wq, p_bq, nullptr, p_proj, p_valh, M_TOT, NQP, CH, 3);
    // 3) deform attention
    deform_kernel<<<M_TOT, dim3(32, 8)>>>(p_valh, p_proj, refp, p_attn);
    // 4) x1 = x + attn @ w_out + b_out
    gemm_tf32<<<dim3(CH / 128, M_TOT / 256), 256, GSMEM>>>(
        p_attn, w_out, b_out, x, p_x1, nullptr, M_TOT, CH, CH, 2);
    // 5) LN2
    ln_kernel<<<lnGrid, lnBlock>>>(p_x1, ln2_g, ln2_b, p_y);
    // 6) h1 = gelu(y @ w_fc1 + b_fc1)
    gemm_tf32<<<dim3(HID / 128, M_TOT / 256), 256, GSMEM>>>(
        p_y, w_fc1, b_fc1, nullptr, p_h1, nullptr, M_TOT, HID, CH, 1);
    // 7) out = x1 + h1 @ w_fc2 + b_fc2
    gemm_tf32<<<dim3(CH / 128, M_TOT / 256), 256, GSMEM>>>(
        p_h1, w_fc2, b_fc2, p_x1, out, nullptr, M_TOT, CH, HID, 2);
}

// round 7
// speedup vs baseline: 3.5559x; 1.3021x over previous
#include <cuda_runtime.h>
#include <cuda_bf16.h>
#include <math.h>

#define LQ     9216
#define NBATCH 2
#define M_TOT  (NBATCH * LQ)     // 18432
#define CH     256
#define HEADS  8
#define NP     25
#define DH     32
#define HID    1024
#define NQP    896               // [val 256 | off 400 | logit 200 | pad 40]
#define OFF_COL  256
#define LOG_COL  656

// ---------------- scratch ----------------
__device__ __nv_bfloat16 g_qh   [M_TOT * CH];
__device__ float         g_proj [M_TOT * NQP];       // off/logit region used
__device__ __nv_bfloat16 g_valh [NBATCH * HEADS * LQ * DH + 64];  // [n,h,pix,ch]
__device__ __nv_bfloat16 g_attnh[M_TOT * CH];
__device__ float         g_x1   [M_TOT * CH];
__device__ __nv_bfloat16 g_yh   [M_TOT * CH];
__device__ __nv_bfloat16 g_h1h  [M_TOT * HID];
__device__ __nv_bfloat16 g_wqh  [CH * NQP];
__device__ float         g_bq   [NQP];
__device__ __nv_bfloat16 g_wouth[CH * CH];
__device__ __nv_bfloat16 g_wfc1h[CH * HID];
__device__ __nv_bfloat16 g_wfc2h[HID * CH];

__device__ __forceinline__ void cp16(void* s, const void* g) {
    unsigned sa = (unsigned)__cvta_generic_to_shared(s);
    asm volatile("cp.async.cg.shared.global [%0], [%1], 16;\n" :: "r"(sa), "l"(g));
}

__device__ __forceinline__ void mma_bf16(float c[4], unsigned a0, unsigned a1,
                                         unsigned a2, unsigned a3,
                                         unsigned b0, unsigned b1) {
    asm volatile(
        "mma.sync.aligned.m16n8k16.row.col.f32.bf16.bf16.f32 "
        "{%0,%1,%2,%3},{%4,%5,%6,%7},{%8,%9},{%0,%1,%2,%3};\n"
        : "+f"(c[0]), "+f"(c[1]), "+f"(c[2]), "+f"(c[3])
        : "r"(a0), "r"(a1), "r"(a2), "r"(a3), "r"(b0), "r"(b1));
}

__device__ __forceinline__ void ldsm_x4(unsigned r[4], unsigned addr) {
    asm volatile("ldmatrix.sync.aligned.m8n8.x4.shared.b16 {%0,%1,%2,%3}, [%4];"
                 : "=r"(r[0]), "=r"(r[1]), "=r"(r[2]), "=r"(r[3]) : "r"(addr));
}
__device__ __forceinline__ void ldsm_x4t(unsigned r[4], unsigned addr) {
    asm volatile("ldmatrix.sync.aligned.m8n8.x4.trans.shared.b16 {%0,%1,%2,%3}, [%4];"
                 : "=r"(r[0]), "=r"(r[1]), "=r"(r[2]), "=r"(r[3]) : "r"(addr));
}

// ---------------- prep: fuse q-weights -> bf16, biases fp32 ----------------
__global__ void prep_wq(const float* __restrict__ w_val, const float* __restrict__ w_off,
                        const float* __restrict__ w_attn, const float* __restrict__ b_val,
                        const float* __restrict__ b_off, const float* __restrict__ b_attn,
                        __nv_bfloat16* __restrict__ wq, float* __restrict__ bq) {
    int col = blockIdx.x * blockDim.x + threadIdx.x;   // 0..895
    int row = blockIdx.y;                              // 0..255
    float v;
    if      (col < 256) v = w_val [row * 256 + col];
    else if (col < 656) v = w_off [row * 400 + (col - 256)];
    else if (col < 856) v = w_attn[row * 200 + (col - 656)];
    else                v = 0.f;
    wq[row * NQP + col] = __float2bfloat16(v);
    if (row == 0) {
        float b;
        if      (col < 256) b = b_val [col];
        else if (col < 656) b = b_off [col - 256];
        else if (col < 856) b = b_attn[col - 656];
        else                b = 0.f;
        bq[col] = b;
    }
}

__global__ void cvt_bf16(const float* __restrict__ src, __nv_bfloat16* __restrict__ dst, int n) {
    int i = blockIdx.x * blockDim.x + threadIdx.x;
    if (i < n) dst[i] = __float2bfloat16(src[i]);
}

// ---------------- LayerNorm (warp/row), bf16 output ----------------
__global__ void ln_kernel(const float* __restrict__ x, const float* __restrict__ g,
                          const float* __restrict__ b, __nv_bfloat16* __restrict__ out) {
    int row  = blockIdx.x * blockDim.y + threadIdx.y;
    int lane = threadIdx.x;
    const float* xr = x + (size_t)row * CH;
    float v[8], s = 0.f, sq = 0.f;
#pragma unroll
    for (int i = 0; i < 8; i++) {
        v[i] = xr[lane + 32 * i];
        s += v[i]; sq += v[i] * v[i];
    }
#pragma unroll
    for (int o = 16; o > 0; o >>= 1) {
        s  += __shfl_xor_sync(0xffffffffu, s,  o);
        sq += __shfl_xor_sync(0xffffffffu, sq, o);
    }
    float mean = s * (1.f / 256.f);
    float var  = sq * (1.f / 256.f) - mean * mean;
    float rstd = rsqrtf(var + 1e-5f);
    __nv_bfloat16* outr = out + (size_t)row * CH;
#pragma unroll
    for (int i = 0; i < 8; i++) {
        int c = lane + 32 * i;
        outr[c] = __float2bfloat16((v[i] - mean) * rstd * g[c] + b[c]);
    }
}

// ---------------- bf16 tensor-core GEMM: C = A[M,K]@B[K,N] + bias ----------------
// CTA 256x128, warp 64x64, BK=32, 3-stage cp.async, ldmatrix fragments.
// epi: 1 = bias+gelu -> bf16 H;  2 = bias + residual R -> fp32 C;
//      3 = proj: col<256 -> bf16 value table H([n,h,pix,ch]); 256..856 -> fp32 C
#define ALD2 56     // A smem row stride (bf16 elements): 32 data + 24 pad
#define BLD2 136    // B smem row stride: 128 data + 8 pad
#define A_ST2 (256 * ALD2)
#define B_ST2 (32 * BLD2)
#define GSMEM ((3 * (A_ST2 + B_ST2)) * 2)

__global__ void __launch_bounds__(256, 1)
gemm_bf16(const __nv_bfloat16* __restrict__ A, const __nv_bfloat16* __restrict__ B,
          const float* __restrict__ bias, const float* __restrict__ R,
          float* __restrict__ C, __nv_bfloat16* __restrict__ H,
          int M, int N, int K, int epi) {
    extern __shared__ __nv_bfloat16 sm2[];
    __nv_bfloat16* Asm = sm2;
    __nv_bfloat16* Bsm = sm2 + 3 * A_ST2;

    int tid = threadIdx.x, lane = tid & 31, warp = tid >> 5;
    int wr = warp >> 1, wc = warp & 1;
    int row0 = blockIdx.y * 256, col0 = blockIdx.x * 128;
    int gID = lane >> 2, tig = lane & 3;

    float acc[4][8][4] = {};
    int ntile = K / 32;

    // ldmatrix lane address offsets (bf16 elements)
    int a_off = (wr * 64 + (lane & 15)) * ALD2 + ((lane >> 4) & 1) * 8;
    int b_off = (lane & 15) * BLD2 + wc * 64 + ((lane >> 4) & 1) * 8;
    unsigned smem_base = (unsigned)__cvta_generic_to_shared(sm2);
    unsigned aAddr[3], bAddr[3];
#pragma unroll
    for (int s = 0; s < 3; s++) {
        aAddr[s] = smem_base + (s * A_ST2 + a_off) * 2;
        bAddr[s] = smem_base + ((3 * A_ST2) + s * B_ST2 + b_off) * 2;
    }

#define LOAD_STAGE(st, t)                                                       \
    {                                                                           \
        __nv_bfloat16* as = Asm + (st) * A_ST2;                                 \
        _Pragma("unroll")                                                       \
        for (int i = 0; i < 4; i++) {                                           \
            int id = tid + i * 256;                                             \
            int r = id >> 2, c8 = (id & 3) * 8;                                 \
            cp16(&as[r * ALD2 + c8], A + (size_t)(row0 + r) * K + (t) * 32 + c8); \
        }                                                                       \
        __nv_bfloat16* bs = Bsm + (st) * B_ST2;                                 \
        _Pragma("unroll")                                                       \
        for (int i = 0; i < 2; i++) {                                           \
            int id = tid + i * 256;                                             \
            int r = id >> 4, c = (id & 15) * 8;                                 \
            cp16(&bs[r * BLD2 + c], B + (size_t)((t) * 32 + r) * N + col0 + c); \
        }                                                                       \
    }

    LOAD_STAGE(0, 0);
    asm volatile("cp.async.commit_group;\n");
    if (ntile > 1) LOAD_STAGE(1, 1);
    asm volatile("cp.async.commit_group;\n");

    for (int t = 0; t < ntile; t++) {
        __syncthreads();
        if (t + 2 < ntile) LOAD_STAGE((t + 2) % 3, t + 2);
        asm volatile("cp.async.commit_group;\n");
        asm volatile("cp.async.wait_group 2;\n");
        __syncthreads();

        int s = t % 3;
#pragma unroll
        for (int step = 0; step < 2; step++) {
            unsigned Af[4][4], Bf[4][4];
#pragma unroll
            for (int mt = 0; mt < 4; mt++)
                ldsm_x4(Af[mt], aAddr[s] + (mt * 16 * ALD2 + step * 16) * 2);
#pragma unroll
            for (int nb = 0; nb < 4; nb++)
                ldsm_x4t(Bf[nb], bAddr[s] + (step * 16 * BLD2 + nb * 16) * 2);
#pragma unroll
            for (int nb = 0; nb < 4; nb++) {
#pragma unroll
                for (int mt = 0; mt < 4; mt++) {
                    mma_bf16(acc[mt][2 * nb],     Af[mt][0], Af[mt][1], Af[mt][2], Af[mt][3], Bf[nb][0], Bf[nb][1]);
                    mma_bf16(acc[mt][2 * nb + 1], Af[mt][0], Af[mt][1], Af[mt][2], Af[mt][3], Bf[nb][2], Bf[nb][3]);
                }
            }
        }
    }

#pragma unroll
    for (int mt = 0; mt < 4; mt++) {
#pragma unroll
        for (int nt = 0; nt < 8; nt++) {
            int row = row0 + wr * 64 + mt * 16 + gID;
            int col = col0 + wc * 64 + nt * 8 + tig * 2;
            if (epi == 3 && col >= 856) continue;
            float b0 = bias[col], b1 = bias[col + 1];
            float v0 = acc[mt][nt][0] + b0;
            float v1 = acc[mt][nt][1] + b1;
            float v2 = acc[mt][nt][2] + b0;
            float v3 = acc[mt][nt][3] + b1;
            if (epi == 1) {
                v0 = 0.5f * v0 * (1.f + erff(v0 * 0.70710678118654752440f));
                v1 = 0.5f * v1 * (1.f + erff(v1 * 0.70710678118654752440f));
                v2 = 0.5f * v2 * (1.f + erff(v2 * 0.70710678118654752440f));
                v3 = 0.5f * v3 * (1.f + erff(v3 * 0.70710678118654752440f));
                *(__nv_bfloat162*)(H + (size_t)row * N + col) = __floats2bfloat162_rn(v0, v1);
                *(__nv_bfloat162*)(H + (size_t)(row + 8) * N + col) = __floats2bfloat162_rn(v2, v3);
            } else if (epi == 3 && col < 256) {
                int h  = col >> 5, dh = col & 31;
                int n_ = row / LQ, pix = row - n_ * LQ;
                __nv_bfloat16* d0 = H + ((size_t)(n_ * HEADS + h) * LQ + pix) * DH + dh;
                *(__nv_bfloat162*)d0 = __floats2bfloat162_rn(v0, v1);
                *(__nv_bfloat162*)(d0 + (size_t)8 * DH) = __floats2bfloat162_rn(v2, v3);
            } else {
                if (epi == 2) {
                    const float* r0 = R + (size_t)row * N + col;
                    const float* r1 = R + (size_t)(row + 8) * N + col;
                    v0 += r0[0]; v1 += r0[1]; v2 += r1[0]; v3 += r1[1];
                }
                float* d0 = C + (size_t)row * N + col;
                float* d1 = C + (size_t)(row + 8) * N + col;
                d0[0] = v0; d0[1] = v1; d1[0] = v2; d1[1] = v3;
            }
        }
    }
}

// ---------------- fused softmax + deformable bilinear attention ----------------
__global__ void deform_kernel(const __nv_bfloat16* __restrict__ valh,
                              const float* __restrict__ proj,
                              const float* __restrict__ refp,
                              __nv_bfloat16* __restrict__ out) {
    int bq   = blockIdx.x;
    int n    = bq / LQ;
    int h    = threadIdx.y;
    int lane = threadIdx.x;

    const float* rowp = proj + (size_t)bq * NQP;
    const float* logr = rowp + LOG_COL + h * NP;

    float lg = (lane < NP) ? logr[lane] : -1e30f;
    float mx = lg;
#pragma unroll
    for (int o = 16; o > 0; o >>= 1) mx = fmaxf(mx, __shfl_xor_sync(0xffffffffu, mx, o));
    float e = (lane < NP) ? expf(lg - mx) : 0.f;
    float sum = e;
#pragma unroll
    for (int o = 16; o > 0; o >>= 1) sum += __shfl_xor_sync(0xffffffffu, sum, o);
    float awn = e / sum;

    int   o0 = 0, o1 = 0;
    float w0lo = 0.f, w0hi = 0.f, w1lo = 0.f, w1hi = 0.f;
    if (lane < NP) {
        const float* offr = rowp + OFF_COL + h * (NP * 2);
        float rx = refp[(size_t)bq * 2 + 0];
        float ry = refp[(size_t)bq * 2 + 1];
        float gx = fmaf(rx, 96.f, offr[2 * lane]     - 0.5f);
        float gy = fmaf(ry, 96.f, offr[2 * lane + 1] - 0.5f);
        float x0f = floorf(gx), y0f = floorf(gy);
        float fx = gx - x0f, fy = gy - y0f;
        int x0 = (int)x0f, y0 = (int)y0f;
        int x1 = x0 + 1,   y1 = y0 + 1;
        int px = min(max(x0, 0), 95);
        float wx0 = (x0 >= 0 && x0 < 96) ? (1.f - fx) : 0.f;
        float wx1 = (x1 >= 0 && x1 < 96) ? fx : 0.f;
        bool at0 = (px == x0);
        float wlo = at0 ? wx0 : wx1;
        float whi = at0 ? wx1 : 0.f;
        float wy0 = (y0 >= 0 && y0 < 96) ? (1.f - fy) : 0.f;
        float wy1 = (y1 >= 0 && y1 < 96) ? fy : 0.f;
        int ry0 = min(max(y0, 0), 95);
        int ry1 = min(max(y1, 0), 95);
        o0 = (ry0 * 96 + px) * (DH * 2);
        o1 = (ry1 * 96 + px) * (DH * 2);
        w0lo = wy0 * wlo * awn;  w0hi = wy0 * whi * awn;
        w1lo = wy1 * wlo * awn;  w1hi = wy1 * whi * awn;
    }

    const char* vb = (const char*)(valh + (size_t)(n * HEADS + h) * LQ * DH) + lane * 4;
    bool lo = (lane < 16);

    float accx = 0.f, accy = 0.f;
#pragma unroll 5
    for (int p = 0; p < NP; p++) {
        int   b0  = __shfl_sync(0xffffffffu, o0, p);
        int   b1  = __shfl_sync(0xffffffffu, o1, p);
        float s0l = __shfl_sync(0xffffffffu, w0lo, p);
        float s0h = __shfl_sync(0xffffffffu, w0hi, p);
        float s1l = __shfl_sync(0xffffffffu, w1lo, p);
        float s1h = __shfl_sync(0xffffffffu, w1hi, p);
        float a0 = lo ? s0l : s0h;
        float a1 = lo ? s1l : s1h;
        float2 v0 = __bfloat1622float2(*(const __nv_bfloat162*)(vb + b0));
        float2 v1 = __bfloat1622float2(*(const __nv_bfloat162*)(vb + b1));
        accx = fmaf(a0, v0.x, accx);
        accy = fmaf(a0, v0.y, accy);
        accx = fmaf(a1, v1.x, accx);
        accy = fmaf(a1, v1.y, accy);
    }
    accx += __shfl_xor_sync(0xffffffffu, accx, 16);
    accy += __shfl_xor_sync(0xffffffffu, accy, 16);

    if (lo) {
        *(__nv_bfloat162*)(out + (size_t)bq * CH + h * DH + lane * 2) =
            __floats2bfloat162_rn(accx, accy);
    }
}

// ---------------- launch ----------------
extern "C" void kernel_launch(void* const* d_in, const int* in_sizes, int n_in,
                              void* d_out, int out_size) {
    const float* x      = (const float*)d_in[0];
    const float* refp   = (const float*)d_in[1];
    const float* ln1_g  = (const float*)d_in[4];
    const float* ln1_b  = (const float*)d_in[5];
    const float* w_off  = (const float*)d_in[6];
    const float* b_off  = (const float*)d_in[7];
    const float* w_attn = (const float*)d_in[8];
    const float* b_attn = (const float*)d_in[9];
    const float* w_val  = (const float*)d_in[10];
    const float* b_val  = (const float*)d_in[11];
    const float* w_out  = (const float*)d_in[12];
    const float* b_out  = (const float*)d_in[13];
    const float* ln2_g  = (const float*)d_in[14];
    const float* ln2_b  = (const float*)d_in[15];
    const float* w_fc1  = (const float*)d_in[16];
    const float* b_fc1  = (const float*)d_in[17];
    const float* w_fc2  = (const float*)d_in[18];
    const float* b_fc2  = (const float*)d_in[19];
    float* out = (float*)d_out;

    float *p_proj, *p_x1, *p_bq;
    __nv_bfloat16 *p_qh, *p_valh, *p_attnh, *p_yh, *p_h1h;
    __nv_bfloat16 *p_wqh, *p_wouth, *p_wfc1h, *p_wfc2h;
    cudaGetSymbolAddress((void**)&p_qh,    g_qh);
    cudaGetSymbolAddress((void**)&p_proj,  g_proj);
    cudaGetSymbolAddress((void**)&p_valh,  g_valh);
    cudaGetSymbolAddress((void**)&p_attnh, g_attnh);
    cudaGetSymbolAddress((void**)&p_x1,    g_x1);
    cudaGetSymbolAddress((void**)&p_yh,    g_yh);
    cudaGetSymbolAddress((void**)&p_h1h,   g_h1h);
    cudaGetSymbolAddress((void**)&p_wqh,   g_wqh);
    cudaGetSymbolAddress((void**)&p_bq,    g_bq);
    cudaGetSymbolAddress((void**)&p_wouth, g_wouth);
    cudaGetSymbolAddress((void**)&p_wfc1h, g_wfc1h);
    cudaGetSymbolAddress((void**)&p_wfc2h, g_wfc2h);

    static bool attr_done = false;
    if (!attr_done) {
        cudaFuncSetAttribute(gemm_bf16, cudaFuncAttributeMaxDynamicSharedMemorySize, GSMEM);
        attr_done = true;
    }

    prep_wq<<<dim3(NQP / 128, CH), 128>>>(w_val, w_off, w_attn, b_val, b_off, b_attn, p_wqh, p_bq);
    cvt_bf16<<<CH * CH  / 256, 256>>>(w_out, p_wouth, CH * CH);
    cvt_bf16<<<CH * HID / 256, 256>>>(w_fc1, p_wfc1h, CH * HID);
    cvt_bf16<<<HID * CH / 256, 256>>>(w_fc2, p_wfc2h, HID * CH);

    dim3 lnBlock(32, 8);
    int  lnGrid = M_TOT / 8;

    // 1) LN1 -> bf16 q
    ln_kernel<<<lnGrid, lnBlock>>>(x, ln1_g, ln1_b, p_qh);
    // 2) fused q-projection: value->bf16 table, off/logit->fp32
    gemm_bf16<<<dim3(NQP / 128, M_TOT / 256), 256, GSMEM>>>(
        p_qh, p_wqh, p_bq, nullptr, p_proj, p_valh, M_TOT, NQP, CH, 3);
    // 3) deform attention -> bf16
    deform_kernel<<<M_TOT, dim3(32, 8)>>>(p_valh, p_proj, refp, p_attnh);
    // 4) x1 = x + attn @ w_out + b_out (fp32)
    gemm_bf16<<<dim3(CH / 128, M_TOT / 256), 256, GSMEM>>>(
        p_attnh, p_wouth, b_out, x, p_x1, nullptr, M_TOT, CH, CH, 2);
    // 5) LN2 -> bf16 y
    ln_kernel<<<lnGrid, lnBlock>>>(p_x1, ln2_g, ln2_b, p_yh);
    // 6) h1 = gelu(y @ w_fc1 + b_fc1) -> bf16
    gemm_bf16<<<dim3(HID / 128, M_TOT / 256), 256, GSMEM>>>(
        p_yh, p_wfc1h, b_fc1, nullptr, nullptr, p_h1h, M_TOT, HID, CH, 1);
    // 7) out = x1 + h1 @ w_fc2 + b_fc2 (fp32)
    gemm_bf16<<<dim3(CH / 128, M_TOT / 256), 256, GSMEM>>>(
        p_h1h, p_wfc2h, b_fc2, p_x1, out, nullptr, M_TOT, CH, HID, 2);
}

// round 8
// speedup vs baseline: 3.9749x; 1.1179x over previous
#include <cuda_runtime.h>
#include <cuda_bf16.h>
#include <math.h>

#define LQ     9216
#define NBATCH 2
#define M_TOT  (NBATCH * LQ)     // 18432
#define CH     256
#define HEADS  8
#define NP     25
#define DH     32
#define HID    1024
#define NQP    896               // [val 256 | off 400 | logit 200 | pad 40]
#define OFF_COL  256
#define LOG_COL  656

#define TBL      (NBATCH * HEADS * LQ * DH)   // value table elements (4,718,592)
#define TBLBYTES (TBL * 2)                    // 9,437,184 (mod 128 == 0)

// ---------------- scratch ----------------
__device__ __nv_bfloat16 g_qh   [M_TOT * CH];
__device__ float         g_proj [M_TOT * NQP];
// two copies: copy0 at 0 (128B aligned), copy1 at element TBL+32 (byte ≡64 mod 128)
__device__ __align__(128) __nv_bfloat16 g_valh[2 * TBL + 96];
__device__ __nv_bfloat16 g_attnh[M_TOT * CH];
__device__ float         g_x1   [M_TOT * CH];
__device__ __nv_bfloat16 g_yh   [M_TOT * CH];
__device__ __nv_bfloat16 g_h1h  [M_TOT * HID];
__device__ __nv_bfloat16 g_wqh  [CH * NQP];
__device__ float         g_bq   [NQP];
__device__ __nv_bfloat16 g_wouth[CH * CH];
__device__ __nv_bfloat16 g_wfc1h[CH * HID];
__device__ __nv_bfloat16 g_wfc2h[HID * CH];

__device__ __forceinline__ void cp16(void* s, const void* g) {
    unsigned sa = (unsigned)__cvta_generic_to_shared(s);
    asm volatile("cp.async.cg.shared.global [%0], [%1], 16;\n" :: "r"(sa), "l"(g));
}

__device__ __forceinline__ void mma_bf16(float c[4], unsigned a0, unsigned a1,
                                         unsigned a2, unsigned a3,
                                         unsigned b0, unsigned b1) {
    asm volatile(
        "mma.sync.aligned.m16n8k16.row.col.f32.bf16.bf16.f32 "
        "{%0,%1,%2,%3},{%4,%5,%6,%7},{%8,%9},{%0,%1,%2,%3};\n"
        : "+f"(c[0]), "+f"(c[1]), "+f"(c[2]), "+f"(c[3])
        : "r"(a0), "r"(a1), "r"(a2), "r"(a3), "r"(b0), "r"(b1));
}

__device__ __forceinline__ void ldsm_x4(unsigned r[4], unsigned addr) {
    asm volatile("ldmatrix.sync.aligned.m8n8.x4.shared.b16 {%0,%1,%2,%3}, [%4];"
                 : "=r"(r[0]), "=r"(r[1]), "=r"(r[2]), "=r"(r[3]) : "r"(addr));
}
__device__ __forceinline__ void ldsm_x4t(unsigned r[4], unsigned addr) {
    asm volatile("ldmatrix.sync.aligned.m8n8.x4.trans.shared.b16 {%0,%1,%2,%3}, [%4];"
                 : "=r"(r[0]), "=r"(r[1]), "=r"(r[2]), "=r"(r[3]) : "r"(addr));
}

// bf16x2 bits -> two f32 via ALU shifts (avoids F2F pipe)
__device__ __forceinline__ float2 bf2f2(unsigned v) {
    float2 r;
    r.x = __uint_as_float(v << 16);
    r.y = __uint_as_float(v & 0xffff0000u);
    return r;
}

// ---------------- prep kernels ----------------
__global__ void prep_wq(const float* __restrict__ w_val, const float* __restrict__ w_off,
                        const float* __restrict__ w_attn, const float* __restrict__ b_val,
                        const float* __restrict__ b_off, const float* __restrict__ b_attn,
                        __nv_bfloat16* __restrict__ wq, float* __restrict__ bq) {
    int col = blockIdx.x * blockDim.x + threadIdx.x;   // 0..895
    int row = blockIdx.y;                              // 0..255
    float v;
    if      (col < 256) v = w_val [row * 256 + col];
    else if (col < 656) v = w_off [row * 400 + (col - 256)];
    else if (col < 856) v = w_attn[row * 200 + (col - 656)];
    else                v = 0.f;
    wq[row * NQP + col] = __float2bfloat16(v);
    if (row == 0) {
        float b;
        if      (col < 256) b = b_val [col];
        else if (col < 656) b = b_off [col - 256];
        else if (col < 856) b = b_attn[col - 656];
        else                b = 0.f;
        bq[col] = b;
    }
}

// one launch converts w_out | w_fc1 | w_fc2
__global__ void cvt3_bf16(const float* __restrict__ w_out, const float* __restrict__ w_fc1,
                          const float* __restrict__ w_fc2, __nv_bfloat16* __restrict__ d_out,
                          __nv_bfloat16* __restrict__ d_fc1, __nv_bfloat16* __restrict__ d_fc2) {
    int i = blockIdx.x * blockDim.x + threadIdx.x;
    if (i < CH * CH) {
        d_out[i] = __float2bfloat16(w_out[i]);
    } else if (i < CH * CH + CH * HID) {
        int j = i - CH * CH;
        d_fc1[j] = __float2bfloat16(w_fc1[j]);
    } else {
        int j = i - CH * CH - CH * HID;
        d_fc2[j] = __float2bfloat16(w_fc2[j]);
    }
}

// ---------------- LayerNorm (warp/row), bf16 output ----------------
__global__ void ln_kernel(const float* __restrict__ x, const float* __restrict__ g,
                          const float* __restrict__ b, __nv_bfloat16* __restrict__ out) {
    int row  = blockIdx.x * blockDim.y + threadIdx.y;
    int lane = threadIdx.x;
    const float* xr = x + (size_t)row * CH;
    float v[8], s = 0.f, sq = 0.f;
#pragma unroll
    for (int i = 0; i < 8; i++) {
        v[i] = xr[lane + 32 * i];
        s += v[i]; sq += v[i] * v[i];
    }
#pragma unroll
    for (int o = 16; o > 0; o >>= 1) {
        s  += __shfl_xor_sync(0xffffffffu, s,  o);
        sq += __shfl_xor_sync(0xffffffffu, sq, o);
    }
    float mean = s * (1.f / 256.f);
    float var  = sq * (1.f / 256.f) - mean * mean;
    float rstd = rsqrtf(var + 1e-5f);
    __nv_bfloat16* outr = out + (size_t)row * CH;
#pragma unroll
    for (int i = 0; i < 8; i++) {
        int c = lane + 32 * i;
        outr[c] = __float2bfloat16((v[i] - mean) * rstd * g[c] + b[c]);
    }
}

// ---------------- bf16 tensor-core GEMM ----------------
// CTA 256x128, warp 64x64, BK=32, 3-stage cp.async, ONE sync per k-tile.
// epi: 1 = bias+gelu -> bf16 H;  2 = bias+residual R -> fp32 C;
//      3 = proj: col<256 -> dual bf16 value tables; 256..856 -> fp32 C
#define ALD2 56
#define BLD2 136
#define A_ST2 (256 * ALD2)
#define B_ST2 (32 * BLD2)
#define GSMEM ((3 * (A_ST2 + B_ST2)) * 2)

__global__ void __launch_bounds__(256, 1)
gemm_bf16(const __nv_bfloat16* __restrict__ A, const __nv_bfloat16* __restrict__ B,
          const float* __restrict__ bias, const float* __restrict__ R,
          float* __restrict__ C, __nv_bfloat16* __restrict__ H,
          int M, int N, int K, int epi) {
    extern __shared__ __nv_bfloat16 sm2[];
    __nv_bfloat16* Asm = sm2;
    __nv_bfloat16* Bsm = sm2 + 3 * A_ST2;

    int tid = threadIdx.x, lane = tid & 31, warp = tid >> 5;
    int wr = warp >> 1, wc = warp & 1;
    int row0 = blockIdx.y * 256, col0 = blockIdx.x * 128;
    int gID = lane >> 2, tig = lane & 3;

    float acc[4][8][4] = {};
    int ntile = K / 32;

    int a_off = (wr * 64 + (lane & 15)) * ALD2 + ((lane >> 4) & 1) * 8;
    int b_off = (lane & 15) * BLD2 + wc * 64 + ((lane >> 4) & 1) * 8;
    unsigned smem_base = (unsigned)__cvta_generic_to_shared(sm2);
    unsigned aAddr[3], bAddr[3];
#pragma unroll
    for (int s = 0; s < 3; s++) {
        aAddr[s] = smem_base + (s * A_ST2 + a_off) * 2;
        bAddr[s] = smem_base + ((3 * A_ST2) + s * B_ST2 + b_off) * 2;
    }

#define LOAD_STAGE(st, t)                                                       \
    {                                                                           \
        __nv_bfloat16* as = Asm + (st) * A_ST2;                                 \
        _Pragma("unroll")                                                       \
        for (int i = 0; i < 4; i++) {                                           \
            int id = tid + i * 256;                                             \
            int r = id >> 2, c8 = (id & 3) * 8;                                 \
            cp16(&as[r * ALD2 + c8], A + (size_t)(row0 + r) * K + (t) * 32 + c8); \
        }                                                                       \
        __nv_bfloat16* bs = Bsm + (st) * B_ST2;                                 \
        _Pragma("unroll")                                                       \
        for (int i = 0; i < 2; i++) {                                           \
            int id = tid + i * 256;                                             \
            int r = id >> 4, c = (id & 15) * 8;                                 \
            cp16(&bs[r * BLD2 + c], B + (size_t)((t) * 32 + r) * N + col0 + c); \
        }                                                                       \
    }

    LOAD_STAGE(0, 0);
    asm volatile("cp.async.commit_group;\n");
    LOAD_STAGE(1, 1);
    asm volatile("cp.async.commit_group;\n");

    for (int t = 0; t < ntile; t++) {
        asm volatile("cp.async.wait_group 1;\n");   // stage t arrived
        __syncthreads();                            // all warps done with stage t-1
        if (t + 2 < ntile) LOAD_STAGE((t + 2) % 3, t + 2);
        asm volatile("cp.async.commit_group;\n");

        int s = t % 3;
#pragma unroll
        for (int step = 0; step < 2; step++) {
            unsigned Af[4][4], Bf[4][4];
#pragma unroll
            for (int mt = 0; mt < 4; mt++)
                ldsm_x4(Af[mt], aAddr[s] + (mt * 16 * ALD2 + step * 16) * 2);
#pragma unroll
            for (int nb = 0; nb < 4; nb++)
                ldsm_x4t(Bf[nb], bAddr[s] + (step * 16 * BLD2 + nb * 16) * 2);
#pragma unroll
            for (int nb = 0; nb < 4; nb++) {
#pragma unroll
                for (int mt = 0; mt < 4; mt++) {
                    mma_bf16(acc[mt][2 * nb],     Af[mt][0], Af[mt][1], Af[mt][2], Af[mt][3], Bf[nb][0], Bf[nb][1]);
                    mma_bf16(acc[mt][2 * nb + 1], Af[mt][0], Af[mt][1], Af[mt][2], Af[mt][3], Bf[nb][2], Bf[nb][3]);
                }
            }
        }
    }

#pragma unroll
    for (int mt = 0; mt < 4; mt++) {
#pragma unroll
        for (int nt = 0; nt < 8; nt++) {
            int row = row0 + wr * 64 + mt * 16 + gID;
            int col = col0 + wc * 64 + nt * 8 + tig * 2;
            if (epi == 3 && col >= 856) continue;
            float b0 = bias[col], b1 = bias[col + 1];
            float v0 = acc[mt][nt][0] + b0;
            float v1 = acc[mt][nt][1] + b1;
            float v2 = acc[mt][nt][2] + b0;
            float v3 = acc[mt][nt][3] + b1;
            if (epi == 1) {
                v0 = 0.5f * v0 * (1.f + erff(v0 * 0.70710678118654752440f));
                v1 = 0.5f * v1 * (1.f + erff(v1 * 0.70710678118654752440f));
                v2 = 0.5f * v2 * (1.f + erff(v2 * 0.70710678118654752440f));
                v3 = 0.5f * v3 * (1.f + erff(v3 * 0.70710678118654752440f));
                *(__nv_bfloat162*)(H + (size_t)row * N + col) = __floats2bfloat162_rn(v0, v1);
                *(__nv_bfloat162*)(H + (size_t)(row + 8) * N + col) = __floats2bfloat162_rn(v2, v3);
            } else if (epi == 3 && col < 256) {
                int h  = col >> 5, dh = col & 31;
                int n_ = row / LQ, pix = row - n_ * LQ;
                __nv_bfloat16* d0 = H + ((size_t)(n_ * HEADS + h) * LQ + pix) * DH + dh;
                __nv_bfloat162 lohi  = __floats2bfloat162_rn(v0, v1);
                __nv_bfloat162 lohi2 = __floats2bfloat162_rn(v2, v3);
                *(__nv_bfloat162*)d0 = lohi;
                *(__nv_bfloat162*)(d0 + (size_t)8 * DH) = lohi2;
                __nv_bfloat16* d1 = d0 + (TBL + 32);             // copy1
                *(__nv_bfloat162*)d1 = lohi;
                *(__nv_bfloat162*)(d1 + (size_t)8 * DH) = lohi2;
            } else {
                if (epi == 2) {
                    const float* r0 = R + (size_t)row * N + col;
                    const float* r1 = R + (size_t)(row + 8) * N + col;
                    v0 += r0[0]; v1 += r0[1]; v2 += r1[0]; v3 += r1[1];
                }
                float* d0 = C + (size_t)row * N + col;
                float* d1 = C + (size_t)(row + 8) * N + col;
                d0[0] = v0; d0[1] = v1; d1[0] = v2; d1[1] = v3;
            }
        }
    }
}

// ---------------- fused softmax + deformable bilinear attention ----------------
// Dual 64B-offset value tables guarantee every 128B patch-row load is 1 L1
// wavefront. Per-point params cached in shared; hot loop = 2 LDS + 2 LDG.
__global__ void deform_kernel(const __nv_bfloat16* __restrict__ valh,
                              const float* __restrict__ proj,
                              const float* __restrict__ refp,
                              __nv_bfloat16* __restrict__ out) {
    __shared__ float4 sA[HEADS][NP + 1];
    __shared__ float2 sB[HEADS][NP + 1];

    int bq   = blockIdx.x;
    int n    = bq / LQ;
    int h    = threadIdx.y;
    int lane = threadIdx.x;

    const float* rowp = proj + (size_t)bq * NQP;
    const float* logr = rowp + LOG_COL + h * NP;

    float lg = (lane < NP) ? logr[lane] : -1e30f;
    float mx = lg;
#pragma unroll
    for (int o = 16; o > 0; o >>= 1) mx = fmaxf(mx, __shfl_xor_sync(0xffffffffu, mx, o));
    float e = (lane < NP) ? expf(lg - mx) : 0.f;
    float sum = e;
#pragma unroll
    for (int o = 16; o > 0; o >>= 1) sum += __shfl_xor_sync(0xffffffffu, sum, o);
    float awn = e / sum;

    if (lane < NP) {
        const float* offr = rowp + OFF_COL + h * (NP * 2);
        float rx = refp[(size_t)bq * 2 + 0];
        float ry = refp[(size_t)bq * 2 + 1];
        float gx = fmaf(rx, 96.f, offr[2 * lane]     - 0.5f);
        float gy = fmaf(ry, 96.f, offr[2 * lane + 1] - 0.5f);
        float x0f = floorf(gx), y0f = floorf(gy);
        float fx = gx - x0f, fy = gy - y0f;
        int x0 = (int)x0f, y0 = (int)y0f;
        int x1 = x0 + 1,   y1 = y0 + 1;
        int px = min(max(x0, 0), 95);
        float wx0 = (x0 >= 0 && x0 < 96) ? (1.f - fx) : 0.f;
        float wx1 = (x1 >= 0 && x1 < 96) ? fx : 0.f;
        bool at0 = (px == x0);
        float wlo = at0 ? wx0 : wx1;
        float whi = at0 ? wx1 : 0.f;
        float wy0 = (y0 >= 0 && y0 < 96) ? (1.f - fy) : 0.f;
        float wy1 = (y1 >= 0 && y1 < 96) ? fy : 0.f;
        int ry0 = min(max(y0, 0), 95);
        int ry1 = min(max(y1, 0), 95);
        int tb = (px & 1) ? (TBLBYTES + 64) : 0;     // copy1 for odd px -> 128B aligned
        int o0 = tb + (ry0 * 96 + px) * (DH * 2);
        int o1 = tb + (ry1 * 96 + px) * (DH * 2);
        sA[h][lane] = make_float4(__int_as_float(o0), __int_as_float(o1),
                                  wy0 * wlo * awn, wy0 * whi * awn);
        sB[h][lane] = make_float2(wy1 * wlo * awn, wy1 * whi * awn);
    }
    __syncwarp();

    const char* vb = (const char*)(valh + (size_t)(n * HEADS + h) * LQ * DH) + lane * 4;
    bool lo = (lane < 16);

    float accx = 0.f, accy = 0.f;
#pragma unroll
    for (int p = 0; p < NP; p++) {
        float4 qa = sA[h][p];
        float2 qb = sB[h][p];
        int   b0 = __float_as_int(qa.x);
        int   b1 = __float_as_int(qa.y);
        float a0 = lo ? qa.z : qa.w;
        float a1 = lo ? qb.x : qb.y;
        float2 v0 = bf2f2(*(const unsigned*)(vb + b0));
        float2 v1 = bf2f2(*(const unsigned*)(vb + b1));
        accx = fmaf(a0, v0.x, accx);
        accy = fmaf(a0, v0.y, accy);
        accx = fmaf(a1, v1.x, accx);
        accy = fmaf(a1, v1.y, accy);
    }
    accx += __shfl_xor_sync(0xffffffffu, accx, 16);
    accy += __shfl_xor_sync(0xffffffffu, accy, 16);

    if (lo) {
        *(__nv_bfloat162*)(out + (size_t)bq * CH + h * DH + lane * 2) =
            __floats2bfloat162_rn(accx, accy);
    }
}

// ---------------- launch ----------------
extern "C" void kernel_launch(void* const* d_in, const int* in_sizes, int n_in,
                              void* d_out, int out_size) {
    const float* x      = (const float*)d_in[0];
    const float* refp   = (const float*)d_in[1];
    const float* ln1_g  = (const float*)d_in[4];
    const float* ln1_b  = (const float*)d_in[5];
    const float* w_off  = (const float*)d_in[6];
    const float* b_off  = (const float*)d_in[7];
    const float* w_attn = (const float*)d_in[8];
    const float* b_attn = (const float*)d_in[9];
    const float* w_val  = (const float*)d_in[10];
    const float* b_val  = (const float*)d_in[11];
    const float* w_out  = (const float*)d_in[12];
    const float* b_out  = (const float*)d_in[13];
    const float* ln2_g  = (const float*)d_in[14];
    const float* ln2_b  = (const float*)d_in[15];
    const float* w_fc1  = (const float*)d_in[16];
    const float* b_fc1  = (const float*)d_in[17];
    const float* w_fc2  = (const float*)d_in[18];
    const float* b_fc2  = (const float*)d_in[19];
    float* out = (float*)d_out;

    float *p_proj, *p_x1, *p_bq;
    __nv_bfloat16 *p_qh, *p_valh, *p_attnh, *p_yh, *p_h1h;
    __nv_bfloat16 *p_wqh, *p_wouth, *p_wfc1h, *p_wfc2h;
    cudaGetSymbolAddress((void**)&p_qh,    g_qh);
    cudaGetSymbolAddress((void**)&p_proj,  g_proj);
    cudaGetSymbolAddress((void**)&p_valh,  g_valh);
    cudaGetSymbolAddress((void**)&p_attnh, g_attnh);
    cudaGetSymbolAddress((void**)&p_x1,    g_x1);
    cudaGetSymbolAddress((void**)&p_yh,    g_yh);
    cudaGetSymbolAddress((void**)&p_h1h,   g_h1h);
    cudaGetSymbolAddress((void**)&p_wqh,   g_wqh);
    cudaGetSymbolAddress((void**)&p_bq,    g_bq);
    cudaGetSymbolAddress((void**)&p_wouth, g_wouth);
    cudaGetSymbolAddress((void**)&p_wfc1h, g_wfc1h);
    cudaGetSymbolAddress((void**)&p_wfc2h, g_wfc2h);

    static bool attr_done = false;
    if (!attr_done) {
        cudaFuncSetAttribute(gemm_bf16, cudaFuncAttributeMaxDynamicSharedMemorySize, GSMEM);
        attr_done = true;
    }

    prep_wq<<<dim3(NQP / 128, CH), 128>>>(w_val, w_off, w_attn, b_val, b_off, b_attn, p_wqh, p_bq);
    cvt3_bf16<<<(CH * CH + CH * HID + HID * CH) / 256, 256>>>(
        w_out, w_fc1, w_fc2, p_wouth, p_wfc1h, p_wfc2h);

    dim3 lnBlock(32, 8);
    int  lnGrid = M_TOT / 8;

    // 1) LN1 -> bf16 q
    ln_kernel<<<lnGrid, lnBlock>>>(x, ln1_g, ln1_b, p_qh);
    // 2) fused q-projection: value -> dual bf16 tables, off/logit -> fp32
    gemm_bf16<<<dim3(NQP / 128, M_TOT / 256), 256, GSMEM>>>(
        p_qh, p_wqh, p_bq, nullptr, p_proj, p_valh, M_TOT, NQP, CH, 3);
    // 3) deform attention -> bf16
    deform_kernel<<<M_TOT, dim3(32, 8)>>>(p_valh, p_proj, refp, p_attnh);
    // 4) x1 = x + attn @ w_out + b_out (fp32)
    gemm_bf16<<<dim3(CH / 128, M_TOT / 256), 256, GSMEM>>>(
        p_attnh, p_wouth, b_out, x, p_x1, nullptr, M_TOT, CH, CH, 2);
    // 5) LN2 -> bf16 y
    ln_kernel<<<lnGrid, lnBlock>>>(p_x1, ln2_g, ln2_b, p_yh);
    // 6) h1 = gelu(y @ w_fc1 + b_fc1) -> bf16
    gemm_bf16<<<dim3(HID / 128, M_TOT / 256), 256, GSMEM>>>(
        p_yh, p_wfc1h, b_fc1, nullptr, nullptr, p_h1h, M_TOT, HID, CH, 1);
    // 7) out = x1 + h1 @ w_fc2 + b_fc2 (fp32)
    gemm_bf16<<<dim3(CH / 128, M_TOT / 256), 256, GSMEM>>>(
        p_h1h, p_wfc2h, b_fc2, p_x1, out, nullptr, M_TOT, CH, HID, 2);
}

// round 9
// speedup vs baseline: 4.3297x; 1.0892x over previous
#include <cuda_runtime.h>
#include <cuda_bf16.h>
#include <math.h>

#define LQ     9216
#define NBATCH 2
#define M_TOT  (NBATCH * LQ)     // 18432
#define CH     256
#define HEADS  8
#define NP     25
#define DH     32
#define HID    1024
#define NQP    896               // [val 256 | off 400 | logit 200 | pad 40]
#define OFF_COL  256
#define LOG_COL  656

#define TBL      (NBATCH * HEADS * LQ * DH)   // value table elements
#define TBLBYTES (TBL * 2)

// ---------------- scratch ----------------
__device__ __nv_bfloat16 g_qh   [M_TOT * CH];
__device__ float         g_proj [M_TOT * NQP];
__device__ __align__(128) __nv_bfloat16 g_valh[2 * TBL + 96];
__device__ __nv_bfloat16 g_attnh[M_TOT * CH];
__device__ float         g_x1   [M_TOT * CH];
__device__ __nv_bfloat16 g_yh   [M_TOT * CH];
__device__ __nv_bfloat16 g_h1h  [M_TOT * HID];
__device__ __nv_bfloat16 g_wqh  [CH * NQP];
__device__ float         g_bq   [NQP];
__device__ __nv_bfloat16 g_wouth[CH * CH];
__device__ __nv_bfloat16 g_wfc1h[CH * HID];
__device__ __nv_bfloat16 g_wfc2h[HID * CH];

__device__ __forceinline__ void cp16(void* s, const void* g) {
    unsigned sa = (unsigned)__cvta_generic_to_shared(s);
    asm volatile("cp.async.cg.shared.global [%0], [%1], 16;\n" :: "r"(sa), "l"(g));
}

__device__ __forceinline__ void mma_bf16(float c[4], unsigned a0, unsigned a1,
                                         unsigned a2, unsigned a3,
                                         unsigned b0, unsigned b1) {
    asm volatile(
        "mma.sync.aligned.m16n8k16.row.col.f32.bf16.bf16.f32 "
        "{%0,%1,%2,%3},{%4,%5,%6,%7},{%8,%9},{%0,%1,%2,%3};\n"
        : "+f"(c[0]), "+f"(c[1]), "+f"(c[2]), "+f"(c[3])
        : "r"(a0), "r"(a1), "r"(a2), "r"(a3), "r"(b0), "r"(b1));
}

__device__ __forceinline__ void ldsm_x4(unsigned r[4], unsigned addr) {
    asm volatile("ldmatrix.sync.aligned.m8n8.x4.shared.b16 {%0,%1,%2,%3}, [%4];"
                 : "=r"(r[0]), "=r"(r[1]), "=r"(r[2]), "=r"(r[3]) : "r"(addr));
}
__device__ __forceinline__ void ldsm_x4t(unsigned r[4], unsigned addr) {
    asm volatile("ldmatrix.sync.aligned.m8n8.x4.trans.shared.b16 {%0,%1,%2,%3}, [%4];"
                 : "=r"(r[0]), "=r"(r[1]), "=r"(r[2]), "=r"(r[3]) : "r"(addr));
}

__device__ __forceinline__ float2 bf2f2(unsigned v) {
    float2 r;
    r.x = __uint_as_float(v << 16);
    r.y = __uint_as_float(v & 0xffff0000u);
    return r;
}

// ---------------- prep kernels ----------------
__global__ void prep_wq(const float* __restrict__ w_val, const float* __restrict__ w_off,
                        const float* __restrict__ w_attn, const float* __restrict__ b_val,
                        const float* __restrict__ b_off, const float* __restrict__ b_attn,
                        __nv_bfloat16* __restrict__ wq, float* __restrict__ bq) {
    int col = blockIdx.x * blockDim.x + threadIdx.x;
    int row = blockIdx.y;
    float v;
    if      (col < 256) v = w_val [row * 256 + col];
    else if (col < 656) v = w_off [row * 400 + (col - 256)];
    else if (col < 856) v = w_attn[row * 200 + (col - 656)];
    else                v = 0.f;
    wq[row * NQP + col] = __float2bfloat16(v);
    if (row == 0) {
        float b;
        if      (col < 256) b = b_val [col];
        else if (col < 656) b = b_off [col - 256];
        else if (col < 856) b = b_attn[col - 656];
        else                b = 0.f;
        bq[col] = b;
    }
}

__global__ void cvt3_bf16(const float* __restrict__ w_out, const float* __restrict__ w_fc1,
                          const float* __restrict__ w_fc2, __nv_bfloat16* __restrict__ d_out,
                          __nv_bfloat16* __restrict__ d_fc1, __nv_bfloat16* __restrict__ d_fc2) {
    int i = blockIdx.x * blockDim.x + threadIdx.x;
    if (i < CH * CH) {
        d_out[i] = __float2bfloat16(w_out[i]);
    } else if (i < CH * CH + CH * HID) {
        int j = i - CH * CH;
        d_fc1[j] = __float2bfloat16(w_fc1[j]);
    } else {
        int j = i - CH * CH - CH * HID;
        d_fc2[j] = __float2bfloat16(w_fc2[j]);
    }
}

// ---------------- LayerNorm (warp/row), bf16 output ----------------
__global__ void ln_kernel(const float* __restrict__ x, const float* __restrict__ g,
                          const float* __restrict__ b, __nv_bfloat16* __restrict__ out) {
    int row  = blockIdx.x * blockDim.y + threadIdx.y;
    int lane = threadIdx.x;
    const float* xr = x + (size_t)row * CH;
    float v[8], s = 0.f, sq = 0.f;
#pragma unroll
    for (int i = 0; i < 8; i++) {
        v[i] = xr[lane + 32 * i];
        s += v[i]; sq += v[i] * v[i];
    }
#pragma unroll
    for (int o = 16; o > 0; o >>= 1) {
        s  += __shfl_xor_sync(0xffffffffu, s,  o);
        sq += __shfl_xor_sync(0xffffffffu, sq, o);
    }
    float mean = s * (1.f / 256.f);
    float var  = sq * (1.f / 256.f) - mean * mean;
    float rstd = rsqrtf(var + 1e-5f);
    __nv_bfloat16* outr = out + (size_t)row * CH;
#pragma unroll
    for (int i = 0; i < 8; i++) {
        int c = lane + 32 * i;
        outr[c] = __float2bfloat16((v[i] - mean) * rstd * g[c] + b[c]);
    }
}

// ---------------- bf16 tensor-core GEMM ----------------
// CTA 128x128, 8 warps (warp tile 32x64), BK=32, 3-stage cp.async, 2 CTAs/SM.
// epi: 1 = bias+gelu -> bf16 H;  2 = bias+residual R -> fp32 C;
//      3 = proj: col<256 -> dual bf16 value tables; 256..856 -> fp32 C
#define ALD2 56
#define BLD2 136
#define A_ST2 (128 * ALD2)
#define B_ST2 (32 * BLD2)
#define GSMEM ((3 * (A_ST2 + B_ST2)) * 2)

__global__ void __launch_bounds__(256, 2)
gemm_bf16(const __nv_bfloat16* __restrict__ A, const __nv_bfloat16* __restrict__ B,
          const float* __restrict__ bias, const float* __restrict__ R,
          float* __restrict__ C, __nv_bfloat16* __restrict__ H,
          int M, int N, int K, int epi) {
    extern __shared__ __nv_bfloat16 sm2[];
    __nv_bfloat16* Asm = sm2;
    __nv_bfloat16* Bsm = sm2 + 3 * A_ST2;

    int tid = threadIdx.x, lane = tid & 31, warp = tid >> 5;
    int wr = warp >> 1, wc = warp & 1;
    int row0 = blockIdx.y * 128, col0 = blockIdx.x * 128;
    int gID = lane >> 2, tig = lane & 3;

    float acc[2][8][4] = {};
    int ntile = K / 32;

    int a_off = (wr * 32 + (lane & 15)) * ALD2 + ((lane >> 4) & 1) * 8;
    int b_off = (lane & 15) * BLD2 + wc * 64 + ((lane >> 4) & 1) * 8;
    unsigned smem_base = (unsigned)__cvta_generic_to_shared(sm2);
    unsigned aAddr[3], bAddr[3];
#pragma unroll
    for (int s = 0; s < 3; s++) {
        aAddr[s] = smem_base + (s * A_ST2 + a_off) * 2;
        bAddr[s] = smem_base + ((3 * A_ST2) + s * B_ST2 + b_off) * 2;
    }

#define LOAD_STAGE(st, t)                                                       \
    {                                                                           \
        __nv_bfloat16* as = Asm + (st) * A_ST2;                                 \
        _Pragma("unroll")                                                       \
        for (int i = 0; i < 2; i++) {                                           \
            int id = tid + i * 256;                                             \
            int r = id >> 2, c8 = (id & 3) * 8;                                 \
            cp16(&as[r * ALD2 + c8], A + (size_t)(row0 + r) * K + (t) * 32 + c8); \
        }                                                                       \
        __nv_bfloat16* bs = Bsm + (st) * B_ST2;                                 \
        _Pragma("unroll")                                                       \
        for (int i = 0; i < 2; i++) {                                           \
            int id = tid + i * 256;                                             \
            int r = id >> 4, c = (id & 15) * 8;                                 \
            cp16(&bs[r * BLD2 + c], B + (size_t)((t) * 32 + r) * N + col0 + c); \
        }                                                                       \
    }

    LOAD_STAGE(0, 0);
    asm volatile("cp.async.commit_group;\n");
    LOAD_STAGE(1, 1);
    asm volatile("cp.async.commit_group;\n");

    for (int t = 0; t < ntile; t++) {
        asm volatile("cp.async.wait_group 1;\n");
        __syncthreads();
        if (t + 2 < ntile) LOAD_STAGE((t + 2) % 3, t + 2);
        asm volatile("cp.async.commit_group;\n");

        int s = t % 3;
#pragma unroll
        for (int step = 0; step < 2; step++) {
            unsigned Af[2][4], Bf[4][4];
#pragma unroll
            for (int mt = 0; mt < 2; mt++)
                ldsm_x4(Af[mt], aAddr[s] + (mt * 16 * ALD2 + step * 16) * 2);
#pragma unroll
            for (int nb = 0; nb < 4; nb++)
                ldsm_x4t(Bf[nb], bAddr[s] + (step * 16 * BLD2 + nb * 16) * 2);
#pragma unroll
            for (int nb = 0; nb < 4; nb++) {
#pragma unroll
                for (int mt = 0; mt < 2; mt++) {
                    mma_bf16(acc[mt][2 * nb],     Af[mt][0], Af[mt][1], Af[mt][2], Af[mt][3], Bf[nb][0], Bf[nb][1]);
                    mma_bf16(acc[mt][2 * nb + 1], Af[mt][0], Af[mt][1], Af[mt][2], Af[mt][3], Bf[nb][2], Bf[nb][3]);
                }
            }
        }
    }

#pragma unroll
    for (int mt = 0; mt < 2; mt++) {
#pragma unroll
        for (int nt = 0; nt < 8; nt++) {
            int row = row0 + wr * 32 + mt * 16 + gID;
            int col = col0 + wc * 64 + nt * 8 + tig * 2;
            if (epi == 3 && col >= 856) continue;
            float b0 = bias[col], b1 = bias[col + 1];
            float v0 = acc[mt][nt][0] + b0;
            float v1 = acc[mt][nt][1] + b1;
            float v2 = acc[mt][nt][2] + b0;
            float v3 = acc[mt][nt][3] + b1;
            if (epi == 1) {
                v0 = 0.5f * v0 * (1.f + erff(v0 * 0.70710678118654752440f));
                v1 = 0.5f * v1 * (1.f + erff(v1 * 0.70710678118654752440f));
                v2 = 0.5f * v2 * (1.f + erff(v2 * 0.70710678118654752440f));
                v3 = 0.5f * v3 * (1.f + erff(v3 * 0.70710678118654752440f));
                *(__nv_bfloat162*)(H + (size_t)row * N + col) = __floats2bfloat162_rn(v0, v1);
                *(__nv_bfloat162*)(H + (size_t)(row + 8) * N + col) = __floats2bfloat162_rn(v2, v3);
            } else if (epi == 3 && col < 256) {
                int h  = col >> 5, dh = col & 31;
                int n_ = row / LQ, pix = row - n_ * LQ;
                __nv_bfloat16* d0 = H + ((size_t)(n_ * HEADS + h) * LQ + pix) * DH + dh;
                __nv_bfloat162 lohi  = __floats2bfloat162_rn(v0, v1);
                __nv_bfloat162 lohi2 = __floats2bfloat162_rn(v2, v3);
                *(__nv_bfloat162*)d0 = lohi;
                *(__nv_bfloat162*)(d0 + (size_t)8 * DH) = lohi2;
                __nv_bfloat16* d1 = d0 + (TBL + 32);
                *(__nv_bfloat162*)d1 = lohi;
                *(__nv_bfloat162*)(d1 + (size_t)8 * DH) = lohi2;
            } else {
                if (epi == 2) {
                    const float* r0 = R + (size_t)row * N + col;
                    const float* r1 = R + (size_t)(row + 8) * N + col;
                    v0 += r0[0]; v1 += r0[1]; v2 += r1[0]; v3 += r1[1];
                }
                float* d0 = C + (size_t)row * N + col;
                float* d1 = C + (size_t)(row + 8) * N + col;
                d0[0] = v0; d0[1] = v1; d1[0] = v2; d1[1] = v3;
            }
        }
    }
}

// ---------------- fused softmax + deformable bilinear attention ----------------
__global__ void deform_kernel(const __nv_bfloat16* __restrict__ valh,
                              const float* __restrict__ proj,
                              const float* __restrict__ refp,
                              __nv_bfloat16* __restrict__ out) {
    __shared__ float4 sA[HEADS][NP + 1];
    __shared__ float2 sB[HEADS][NP + 1];

    int bq   = blockIdx.x;
    int n    = bq / LQ;
    int h    = threadIdx.y;
    int lane = threadIdx.x;

    const float* rowp = proj + (size_t)bq * NQP;
    const float* logr = rowp + LOG_COL + h * NP;

    float lg = (lane < NP) ? logr[lane] : -1e30f;
    float mx = lg;
#pragma unroll
    for (int o = 16; o > 0; o >>= 1) mx = fmaxf(mx, __shfl_xor_sync(0xffffffffu, mx, o));
    float e = (lane < NP) ? expf(lg - mx) : 0.f;
    float sum = e;
#pragma unroll
    for (int o = 16; o > 0; o >>= 1) sum += __shfl_xor_sync(0xffffffffu, sum, o);
    float awn = e / sum;

    if (lane < NP) {
        const float* offr = rowp + OFF_COL + h * (NP * 2);
        float rx = refp[(size_t)bq * 2 + 0];
        float ry = refp[(size_t)bq * 2 + 1];
        float gx = fmaf(rx, 96.f, offr[2 * lane]     - 0.5f);
        float gy = fmaf(ry, 96.f, offr[2 * lane + 1] - 0.5f);
        float x0f = floorf(gx), y0f = floorf(gy);
        float fx = gx - x0f, fy = gy - y0f;
        int x0 = (int)x0f, y0 = (int)y0f;
        int x1 = x0 + 1,   y1 = y0 + 1;
        int px = min(max(x0, 0), 95);
        float wx0 = (x0 >= 0 && x0 < 96) ? (1.f - fx) : 0.f;
        float wx1 = (x1 >= 0 && x1 < 96) ? fx : 0.f;
        bool at0 = (px == x0);
        float wlo = at0 ? wx0 : wx1;
        float whi = at0 ? wx1 : 0.f;
        float wy0 = (y0 >= 0 && y0 < 96) ? (1.f - fy) : 0.f;
        float wy1 = (y1 >= 0 && y1 < 96) ? fy : 0.f;
        int ry0 = min(max(y0, 0), 95);
        int ry1 = min(max(y1, 0), 95);
        int tb = (px & 1) ? (TBLBYTES + 64) : 0;
        int o0 = tb + (ry0 * 96 + px) * (DH * 2);
        int o1 = tb + (ry1 * 96 + px) * (DH * 2);
        sA[h][lane] = make_float4(__int_as_float(o0), __int_as_float(o1),
                                  wy0 * wlo * awn, wy0 * whi * awn);
        sB[h][lane] = make_float2(wy1 * wlo * awn, wy1 * whi * awn);
    }
    __syncwarp();

    const char* vb = (const char*)(valh + (size_t)(n * HEADS + h) * LQ * DH) + lane * 4;
    bool lo = (lane < 16);

    float accx = 0.f, accy = 0.f;
#pragma unroll
    for (int p = 0; p < NP; p++) {
        float4 qa = sA[h][p];
        float2 qb = sB[h][p];
        int   b0 = __float_as_int(qa.x);
        int   b1 = __float_as_int(qa.y);
        float a0 = lo ? qa.z : qa.w;
        float a1 = lo ? qb.x : qb.y;
        float2 v0 = bf2f2(*(const unsigned*)(vb + b0));
        float2 v1 = bf2f2(*(const unsigned*)(vb + b1));
        accx = fmaf(a0, v0.x, accx);
        accy = fmaf(a0, v0.y, accy);
        accx = fmaf(a1, v1.x, accx);
        accy = fmaf(a1, v1.y, accy);
    }
    accx += __shfl_xor_sync(0xffffffffu, accx, 16);
    accy += __shfl_xor_sync(0xffffffffu, accy, 16);

    if (lo) {
        *(__nv_bfloat162*)(out + (size_t)bq * CH + h * DH + lane * 2) =
            __floats2bfloat162_rn(accx, accy);
    }
}

// ---------------- launch ----------------
extern "C" void kernel_launch(void* const* d_in, const int* in_sizes, int n_in,
                              void* d_out, int out_size) {
    const float* x      = (const float*)d_in[0];
    const float* refp   = (const float*)d_in[1];
    const float* ln1_g  = (const float*)d_in[4];
    const float* ln1_b  = (const float*)d_in[5];
    const float* w_off  = (const float*)d_in[6];
    const float* b_off  = (const float*)d_in[7];
    const float* w_attn = (const float*)d_in[8];
    const float* b_attn = (const float*)d_in[9];
    const float* w_val  = (const float*)d_in[10];
    const float* b_val  = (const float*)d_in[11];
    const float* w_out  = (const float*)d_in[12];
    const float* b_out  = (const float*)d_in[13];
    const float* ln2_g  = (const float*)d_in[14];
    const float* ln2_b  = (const float*)d_in[15];
    const float* w_fc1  = (const float*)d_in[16];
    const float* b_fc1  = (const float*)d_in[17];
    const float* w_fc2  = (const float*)d_in[18];
    const float* b_fc2  = (const float*)d_in[19];
    float* out = (float*)d_out;

    float *p_proj, *p_x1, *p_bq;
    __nv_bfloat16 *p_qh, *p_valh, *p_attnh, *p_yh, *p_h1h;
    __nv_bfloat16 *p_wqh, *p_wouth, *p_wfc1h, *p_wfc2h;
    cudaGetSymbolAddress((void**)&p_qh,    g_qh);
    cudaGetSymbolAddress((void**)&p_proj,  g_proj);
    cudaGetSymbolAddress((void**)&p_valh,  g_valh);
    cudaGetSymbolAddress((void**)&p_attnh, g_attnh);
    cudaGetSymbolAddress((void**)&p_x1,    g_x1);
    cudaGetSymbolAddress((void**)&p_yh,    g_yh);
    cudaGetSymbolAddress((void**)&p_h1h,   g_h1h);
    cudaGetSymbolAddress((void**)&p_wqh,   g_wqh);
    cudaGetSymbolAddress((void**)&p_bq,    g_bq);
    cudaGetSymbolAddress((void**)&p_wouth, g_wouth);
    cudaGetSymbolAddress((void**)&p_wfc1h, g_wfc1h);
    cudaGetSymbolAddress((void**)&p_wfc2h, g_wfc2h);

    static bool attr_done = false;
    if (!attr_done) {
        cudaFuncSetAttribute(gemm_bf16, cudaFuncAttributeMaxDynamicSharedMemorySize, GSMEM);
        attr_done = true;
    }

    prep_wq<<<dim3(NQP / 128, CH), 128>>>(w_val, w_off, w_attn, b_val, b_off, b_attn, p_wqh, p_bq);
    cvt3_bf16<<<(CH * CH + CH * HID + HID * CH) / 256, 256>>>(
        w_out, w_fc1, w_fc2, p_wouth, p_wfc1h, p_wfc2h);

    dim3 lnBlock(32, 8);
    int  lnGrid = M_TOT / 8;

    // 1) LN1 -> bf16 q
    ln_kernel<<<lnGrid, lnBlock>>>(x, ln1_g, ln1_b, p_qh);
    // 2) fused q-projection: value -> dual bf16 tables, off/logit -> fp32
    gemm_bf16<<<dim3(NQP / 128, M_TOT / 128), 256, GSMEM>>>(
        p_qh, p_wqh, p_bq, nullptr, p_proj, p_valh, M_TOT, NQP, CH, 3);
    // 3) deform attention -> bf16
    deform_kernel<<<M_TOT, dim3(32, 8)>>>(p_valh, p_proj, refp, p_attnh);
    // 4) x1 = x + attn @ w_out + b_out (fp32)
    gemm_bf16<<<dim3(CH / 128, M_TOT / 128), 256, GSMEM>>>(
        p_attnh, p_wouth, b_out, x, p_x1, nullptr, M_TOT, CH, CH, 2);
    // 5) LN2 -> bf16 y
    ln_kernel<<<lnGrid, lnBlock>>>(p_x1, ln2_g, ln2_b, p_yh);
    // 6) h1 = gelu(y @ w_fc1 + b_fc1) -> bf16
    gemm_bf16<<<dim3(HID / 128, M_TOT / 128), 256, GSMEM>>>(
        p_yh, p_wfc1h, b_fc1, nullptr, nullptr, p_h1h, M_TOT, HID, CH, 1);
    // 7) out = x1 + h1 @ w_fc2 + b_fc2 (fp32)
    gemm_bf16<<<dim3(CH / 128, M_TOT / 128), 256, GSMEM>>>(
        p_h1h, p_wfc2h, b_fc2, p_x1, out, nullptr, M_TOT, CH, HID, 2);
}